// round 2
// baseline (speedup 1.0000x reference)
#include <cuda_runtime.h>
#include <cuda_bf16.h>
#include <math.h>

#define T_   3072
#define DIM_ 1024
#define H_   8
#define D_   128

typedef unsigned long long ull;

// ---------------- scratch (device globals: no allocation allowed) ----------
__device__ float g_qkv[(size_t)T_ * 3 * DIM_];
__device__ float g_q   [(size_t)T_ * DIM_];
__device__ float g_krot[(size_t)T_ * DIM_];
__device__ float g_v   [(size_t)T_ * DIM_];
__device__ float g_y   [(size_t)T_ * DIM_];
__device__ float g_gate[T_ * H_];

// ---------------- f32x2 helpers --------------------------------------------
__device__ __forceinline__ unsigned su(const void* p) {
    return (unsigned)__cvta_generic_to_shared(p);
}
__device__ __forceinline__ void lds2(ull& a, ull& b, unsigned addr) {
    asm volatile("ld.shared.v2.u64 {%0,%1},[%2];" : "=l"(a), "=l"(b) : "r"(addr));
}
__device__ __forceinline__ void sts64(unsigned addr, ull v) {
    asm volatile("st.shared.u64 [%0],%1;" :: "r"(addr), "l"(v) : "memory");
}
__device__ __forceinline__ void ffma2(ull& d, ull a, ull b) {
    asm("fma.rn.f32x2 %0,%1,%2,%0;" : "+l"(d) : "l"(a), "l"(b));
}
__device__ __forceinline__ void fmul2(ull& d, ull a) {
    asm("mul.rn.f32x2 %0,%0,%1;" : "+l"(d) : "l"(a));
}
__device__ __forceinline__ ull fdup(float x) {
    ull r; asm("mov.b64 %0,{%1,%1};" : "=l"(r) : "f"(x)); return r;
}
__device__ __forceinline__ float2 funpk(ull v) {
    float2 f; asm("mov.b64 {%0,%1},%2;" : "=f"(f.x), "=f"(f.y) : "l"(v)); return f;
}

// ---------------- SGEMM (FFMA2): C = lam * A @ B^T --------------------------
// A:[M,K], B:[N,K] row-major. Tile 128x128x16, 256 threads, M-packed f32x2.
#define BSTR 264
__global__ __launch_bounds__(256, 2) void sgemm_abt_f2(
    const float* __restrict__ A, const float* __restrict__ B,
    float* __restrict__ C, int M, int N, int K,
    const float* __restrict__ lam, int lidx)
{
    __shared__ float As[16 * 128];    // k-major: As[kk][row]
    __shared__ float Bsd[16 * BSTR];  // k-major duplicated: Bsd[kk][2*col{,+1}]
    const int tid = threadIdx.x;
    const int m0 = blockIdx.y * 128;
    const int n0 = blockIdx.x * 128;
    const int ty = tid >> 4, tx = tid & 15;
    const int lrow = tid >> 2;        // 0..63
    const int lkc  = (tid & 3) << 2;  // 0,4,8,12
    const unsigned sA = su(As), sB = su(Bsd);

    ull acc[4][8];
#pragma unroll
    for (int p = 0; p < 4; p++)
#pragma unroll
        for (int c = 0; c < 8; c++) acc[p][c] = 0ull;

    const float* A0 = A + (size_t)(m0 + lrow)      * K + lkc;
    const float* A1 = A + (size_t)(m0 + lrow + 64) * K + lkc;
    const float* B0 = B + (size_t)(n0 + lrow)      * K + lkc;
    const float* B1 = B + (size_t)(n0 + lrow + 64) * K + lkc;

    float4 a0 = *(const float4*)A0, a1 = *(const float4*)A1;
    float4 b0 = *(const float4*)B0, b1 = *(const float4*)B1;

    for (int k0 = 0; k0 < K; k0 += 16) {
        __syncthreads();
        {
            const float* av0 = (const float*)&a0;
            const float* av1 = (const float*)&a1;
            const float* bv0 = (const float*)&b0;
            const float* bv1 = (const float*)&b1;
#pragma unroll
            for (int kq = 0; kq < 4; kq++) {
                As[(lkc + kq) * 128 + lrow]      = av0[kq];
                As[(lkc + kq) * 128 + lrow + 64] = av1[kq];
                sts64(sB + ((lkc + kq) * BSTR + 2 * lrow) * 4,        fdup(bv0[kq]));
                sts64(sB + ((lkc + kq) * BSTR + 2 * (lrow + 64)) * 4, fdup(bv1[kq]));
            }
        }
        if (k0 + 16 < K) {  // prefetch next tile
            a0 = *(const float4*)(A0 + k0 + 16);
            a1 = *(const float4*)(A1 + k0 + 16);
            b0 = *(const float4*)(B0 + k0 + 16);
            b1 = *(const float4*)(B1 + k0 + 16);
        }
        __syncthreads();

#pragma unroll
        for (int kk = 0; kk < 16; kk++) {
            ull a2[4], bd[8];
            lds2(a2[0], a2[1], sA + (kk * 128 + ty * 8) * 4);
            lds2(a2[2], a2[3], sA + (kk * 128 + ty * 8 + 4) * 4);
            lds2(bd[0], bd[1], sB + (kk * BSTR + 8 * tx) * 4);
            lds2(bd[2], bd[3], sB + (kk * BSTR + 8 * tx + 4) * 4);
            lds2(bd[4], bd[5], sB + (kk * BSTR + 8 * tx + 128) * 4);
            lds2(bd[6], bd[7], sB + (kk * BSTR + 8 * tx + 132) * 4);
#pragma unroll
            for (int p = 0; p < 4; p++)
#pragma unroll
                for (int c = 0; c < 8; c++)
                    ffma2(acc[p][c], a2[p], bd[c]);
        }
    }

    const float alpha = lam[lidx];
#pragma unroll
    for (int p = 0; p < 4; p++) {
        float2 u[8];
#pragma unroll
        for (int c = 0; c < 8; c++) u[c] = funpk(acc[p][c]);
        const int r0 = m0 + ty * 8 + 2 * p;
        float* c0p = C + (size_t)r0 * N + n0 + 4 * tx;
        float* c1p = c0p + N;
        float4 w;
        w.x = alpha*u[0].x; w.y = alpha*u[1].x; w.z = alpha*u[2].x; w.w = alpha*u[3].x;
        *(float4*)c0p = w;
        w.x = alpha*u[4].x; w.y = alpha*u[5].x; w.z = alpha*u[6].x; w.w = alpha*u[7].x;
        *(float4*)(c0p + 64) = w;
        w.x = alpha*u[0].y; w.y = alpha*u[1].y; w.z = alpha*u[2].y; w.w = alpha*u[3].y;
        *(float4*)c1p = w;
        w.x = alpha*u[4].y; w.y = alpha*u[5].y; w.z = alpha*u[6].y; w.w = alpha*u[7].y;
        *(float4*)(c1p + 64) = w;
    }
}

// ------------- postprocess: rmsnorm + rotary + gates + ve add --------------
__global__ __launch_bounds__(256) void postproc_kernel(
    const float* __restrict__ x, const float* __restrict__ ve,
    const float* __restrict__ ve_gate_w, const float* __restrict__ attn_gate_w,
    const float* __restrict__ cosb, const float* __restrict__ sinb)
{
    const int t    = blockIdx.x;
    const int w    = threadIdx.x >> 5;
    const int lane = threadIdx.x & 31;
    const float* base = g_qkv + (size_t)t * (3 * DIM_);

    const float c0 = cosb[t * 64 + lane],      s0 = sinb[t * 64 + lane];
    const float c1 = cosb[t * 64 + lane + 32], s1 = sinb[t * 64 + lane + 32];

    {
        const float* qb = base + w * D_;
        float a0 = qb[lane], a1 = qb[lane + 32], a2 = qb[lane + 64], a3 = qb[lane + 96];
        float ss = a0*a0 + a1*a1 + a2*a2 + a3*a3;
#pragma unroll
        for (int off = 16; off; off >>= 1) ss += __shfl_xor_sync(0xffffffffu, ss, off);
        float r = rsqrtf(ss * (1.0f / 128.0f) + 1e-6f);
        a0 *= r; a1 *= r; a2 *= r; a3 *= r;
        float* qp = g_q + (size_t)t * DIM_ + w * D_;
        qp[lane]      =  a0 * c0 + a2 * s0;
        qp[lane + 32] =  a1 * c1 + a3 * s1;
        qp[lane + 64] = -a0 * s0 + a2 * c0;
        qp[lane + 96] = -a1 * s1 + a3 * c1;
    }
    {
        const float* kb = base + DIM_ + w * D_;
        float a0 = kb[lane], a1 = kb[lane + 32], a2 = kb[lane + 64], a3 = kb[lane + 96];
        float ss = a0*a0 + a1*a1 + a2*a2 + a3*a3;
#pragma unroll
        for (int off = 16; off; off >>= 1) ss += __shfl_xor_sync(0xffffffffu, ss, off);
        float r = rsqrtf(ss * (1.0f / 128.0f) + 1e-6f);
        a0 *= r; a1 *= r; a2 *= r; a3 *= r;
        float* kp = g_krot + (size_t)t * DIM_ + w * D_;
        kp[lane]      =  a0 * c0 + a2 * s0;
        kp[lane + 32] =  a1 * c1 + a3 * s1;
        kp[lane + 64] = -a0 * s0 + a2 * c0;
        kp[lane + 96] = -a1 * s1 + a3 * c1;
    }
    float xv = (lane < 16) ? x[(size_t)t * DIM_ + lane] : 0.f;
    float dv = (lane < 16) ? xv * ve_gate_w[w * 16 + lane]   : 0.f;
    float da = (lane < 16) ? xv * attn_gate_w[w * 16 + lane] : 0.f;
#pragma unroll
    for (int off = 16; off; off >>= 1) {
        dv += __shfl_xor_sync(0xffffffffu, dv, off);
        da += __shfl_xor_sync(0xffffffffu, da, off);
    }
    const float veg = 2.0f / (1.0f + __expf(-dv));
    if (lane == 0) g_gate[t * H_ + w] = 1.0f / (1.0f + __expf(-da));
    {
        const float* vb = base + 2 * DIM_ + w * D_;
        const float* vp2 = ve + (size_t)t * DIM_ + w * D_;
        float* vp = g_v + (size_t)t * DIM_ + w * D_;
        vp[lane]      = vb[lane]      + veg * vp2[lane];
        vp[lane + 32] = vb[lane + 32] + veg * vp2[lane + 32];
        vp[lane + 64] = vb[lane + 64] + veg * vp2[lane + 64];
        vp[lane + 96] = vb[lane + 96] + veg * vp2[lane + 96];
    }
}

// ------------- flash attention (FFMA2, 64x64 tiles, fused k-shift) ---------
#define AST 132
#define ATTN_SMEM ((3 * 64 * AST) * 4 + 128 * 4)

__device__ __forceinline__ float rmax16(float v) {
#pragma unroll
    for (int off = 8; off; off >>= 1)
        v = fmaxf(v, __shfl_xor_sync(0xffffffffu, v, off, 16));
    return v;
}
__device__ __forceinline__ float rsum16(float v) {
#pragma unroll
    for (int off = 8; off; off >>= 1)
        v += __shfl_xor_sync(0xffffffffu, v, off, 16);
    return v;
}

__global__ __launch_bounds__(256) void attn_kernel(
    const int* __restrict__ seg, const int* __restrict__ bm_ptr)
{
    extern __shared__ float sm[];
    float* Qs  = sm;                  // 64 x AST (d-contiguous)
    float* KPs = Qs + 64 * AST;       // K tile; reused as duplicated-P
    float* Vs  = KPs + 64 * AST;
    int*  qseg = (int*)(Vs + 64 * AST);
    int*  kseg = qseg + 64;

    const int h   = blockIdx.y;
    const int m0  = blockIdx.x * 64;
    const int tid = threadIdx.x;
    const int ty  = tid >> 4, tx = tid & 15;
    const int bm  = bm_ptr[0];
    const unsigned sQ = su(Qs), sK = su(KPs), sV = su(Vs);

    // load Q tile [64 x 128]
#pragma unroll
    for (int i = 0; i < 8; i++) {
        int idx = tid + i * 256;
        int r = idx >> 5, c4 = idx & 31;
        *(float4*)&Qs[r * AST + c4 * 4] =
            *(const float4*)&g_q[(size_t)(m0 + r) * DIM_ + h * D_ + c4 * 4];
    }
    if (tid < 64) qseg[tid] = seg[m0 + tid];
    __syncthreads();

    ull  O2[4][4];
    float m_i[4], l_i[4];
#pragma unroll
    for (int i = 0; i < 4; i++) {
        m_i[i] = -1e30f; l_i[i] = 0.f;
#pragma unroll
        for (int g = 0; g < 4; g++) O2[i][g] = 0ull;
    }

    const int qs0 = seg[m0], qs1 = seg[m0 + 63];
    int kb_lo = m0 - bm; if (kb_lo < 0) kb_lo = 0; kb_lo >>= 6;
    const int kb_hi = m0 >> 6;

    unsigned qb[4], kbase[4], pb[4];
#pragma unroll
    for (int i = 0; i < 4; i++) {
        qb[i] = sQ + ((ty * 4 + i) * AST) * 4;
        pb[i] = sK + ((ty * 4 + i) * AST) * 4;
        kbase[i] = sK + ((tx + 16 * i) * AST) * 4;
    }

    for (int kb = kb_lo; kb <= kb_hi; kb++) {
        const int s0 = kb * 64;
        const int ks0 = seg[s0], ks1 = seg[s0 + 63];
        if (ks1 < qs0 || ks0 > qs1) continue;

        // load K (with fused quarter-shift) and V
#pragma unroll
        for (int i = 0; i < 8; i++) {
            int idx = tid + i * 256;
            int r = idx >> 5, c4 = idx & 31;
            int t = s0 + r;
            int ts = ((c4 >> 3) & 1) ? (t > 0 ? t - 1 : 0) : t;
            *(float4*)&KPs[r * AST + c4 * 4] =
                *(const float4*)&g_krot[(size_t)ts * DIM_ + h * D_ + c4 * 4];
            *(float4*)&Vs[r * AST + c4 * 4] =
                *(const float4*)&g_v[(size_t)t * DIM_ + h * D_ + c4 * 4];
        }
        if (tid < 64) kseg[tid] = seg[s0 + tid];
        __syncthreads();

        // S = Q K^T, packed over d
        ull s2[4][4];
#pragma unroll
        for (int i = 0; i < 4; i++)
#pragma unroll
            for (int j = 0; j < 4; j++) s2[i][j] = 0ull;

#pragma unroll 4
        for (int d4 = 0; d4 < 32; d4++) {
            ull qa[4][2], ka[4][2];
#pragma unroll
            for (int i = 0; i < 4; i++) lds2(qa[i][0], qa[i][1], qb[i] + d4 * 16);
#pragma unroll
            for (int j = 0; j < 4; j++) lds2(ka[j][0], ka[j][1], kbase[j] + d4 * 16);
#pragma unroll
            for (int i = 0; i < 4; i++)
#pragma unroll
                for (int j = 0; j < 4; j++) {
                    ffma2(s2[i][j], qa[i][0], ka[j][0]);
                    ffma2(s2[i][j], qa[i][1], ka[j][1]);
                }
        }
        __syncthreads();   // all K reads done; KPs becomes P-dup

        // mask + online softmax; write duplicated P into KPs
#pragma unroll
        for (int i = 0; i < 4; i++) {
            const int tq = m0 + ty * 4 + i;
            const int sq = qseg[ty * 4 + i];
            float sv[4];
            float rowmax = -1e30f;
#pragma unroll
            for (int j = 0; j < 4; j++) {
                float2 f = funpk(s2[i][j]);
                float s = f.x + f.y;
                const int tk = s0 + tx + 16 * j;
                bool valid = (tk <= tq) && (tk >= tq - bm) && (kseg[tx + 16 * j] == sq);
                sv[j] = valid ? s * 0.1f : -1e30f;
                rowmax = fmaxf(rowmax, sv[j]);
            }
            rowmax = rmax16(rowmax);
            const float newm  = fmaxf(m_i[i], rowmax);
            const float alpha = __expf(m_i[i] - newm);
            m_i[i] = newm;
            float rs = 0.f;
#pragma unroll
            for (int j = 0; j < 4; j++) {
                float p = __expf(sv[j] - newm);
                sts64(pb[i] + (2 * (tx + 16 * j)) * 4, fdup(p));
                rs += p;
            }
            rs = rsum16(rs);
            l_i[i] = l_i[i] * alpha + rs;
            ull a2 = fdup(alpha);
#pragma unroll
            for (int g = 0; g < 4; g++) fmul2(O2[i][g], a2);
        }
        __syncthreads();

        // O += P V, packed over col-pairs
#pragma unroll 4
        for (int s2i = 0; s2i < 32; s2i++) {
            ull pd[4][2], v0[4], v1[4];
#pragma unroll
            for (int i = 0; i < 4; i++) lds2(pd[i][0], pd[i][1], pb[i] + s2i * 16);
            {
                unsigned vb = sV + ((2 * s2i) * AST + 4 * tx) * 4;
                lds2(v0[0], v0[1], vb);
                lds2(v0[2], v0[3], vb + 64 * 4);
                vb += AST * 4;
                lds2(v1[0], v1[1], vb);
                lds2(v1[2], v1[3], vb + 64 * 4);
            }
#pragma unroll
            for (int i = 0; i < 4; i++)
#pragma unroll
                for (int g = 0; g < 4; g++) {
                    ffma2(O2[i][g], pd[i][0], v0[g]);
                    ffma2(O2[i][g], pd[i][1], v1[g]);
                }
        }
        __syncthreads();
    }

    // epilogue: normalize, gate, store
#pragma unroll
    for (int i = 0; i < 4; i++) {
        const int tq = m0 + ty * 4 + i;
        const float g = g_gate[tq * H_ + h];
        const float inv = g / l_i[i];
        float2 u0 = funpk(O2[i][0]), u1 = funpk(O2[i][1]);
        float2 u2 = funpk(O2[i][2]), u3 = funpk(O2[i][3]);
        float* yp = g_y + (size_t)tq * DIM_ + h * D_ + 4 * tx;
        float4 w;
        w.x = u0.x * inv; w.y = u0.y * inv; w.z = u1.x * inv; w.w = u1.y * inv;
        *(float4*)yp = w;
        w.x = u2.x * inv; w.y = u2.y * inv; w.z = u3.x * inv; w.w = u3.y * inv;
        *(float4*)(yp + 64) = w;
    }
}

// ---------------------------------------------------------------------------
extern "C" void kernel_launch(void* const* d_in, const int* in_sizes, int n_in,
                              void* d_out, int out_size)
{
    const float* x    = (const float*)d_in[0];
    const float* qkvo = (const float*)d_in[1];
    const float* lam  = (const float*)d_in[2];
    const float* ve   = (const float*)d_in[3];
    const float* agw  = (const float*)d_in[4];
    const float* vgw  = (const float*)d_in[5];
    const float* cosb = (const float*)d_in[6];
    const float* sinb = (const float*)d_in[7];
    const int*   seg  = (const int*)d_in[8];
    const int*   bmp  = (const int*)d_in[9];
    float*       out  = (float*)d_out;

    float *p_qkv, *p_y;
    cudaGetSymbolAddress((void**)&p_qkv, g_qkv);
    cudaGetSymbolAddress((void**)&p_y,   g_y);

    // 1. qkv = lam0 * x @ Wqkv^T   [3072 x 3072]
    sgemm_abt_f2<<<dim3(3072 / 128, 3072 / 128), 256>>>(
        x, qkvo, p_qkv, T_, 3 * DIM_, DIM_, lam, 0);

    // 2. rmsnorm + rotary + gates + ve add
    postproc_kernel<<<T_, 256>>>(x, ve, vgw, agw, cosb, sinb);

    // 3. attention (k-shift fused into K-tile load)
    cudaFuncSetAttribute(attn_kernel,
                         cudaFuncAttributeMaxDynamicSharedMemorySize, ATTN_SMEM);
    attn_kernel<<<dim3(T_ / 64, H_), 256, ATTN_SMEM>>>(seg, bmp);

    // 4. out = lam1 * y @ Wo^T   [3072 x 1024]
    sgemm_abt_f2<<<dim3(1024 / 128, 3072 / 128), 256>>>(
        p_y, qkvo + 3 * DIM_ * DIM_, out, T_, DIM_, DIM_, lam, 1);
}

// round 4
// speedup vs baseline: 1.3316x; 1.3316x over previous
#include <cuda_runtime.h>
#include <cuda_bf16.h>
#include <math.h>
#include <stdint.h>

#define T_   3072
#define DIM_ 1024
#define H_   8
#define D_   128

// ---------------- scratch (device globals: no allocation allowed) ----------
__device__ float g_qkv[(size_t)T_ * 3 * DIM_];
__device__ float g_q   [(size_t)T_ * DIM_];
__device__ float g_krot[(size_t)T_ * DIM_];
__device__ float g_k   [(size_t)T_ * DIM_];
__device__ float g_v   [(size_t)T_ * DIM_];
__device__ float g_y   [(size_t)T_ * DIM_];
__device__ float g_gate[T_ * H_];

// ============================================================================
// bf16-split mma.sync GEMM:  C[m,n] = lam * sum_k A[m,k]*B[n,k],  K=1024
// Tile 128x128, 8 warps (2x4), K-chunk 32, double buffer, 3-term compensation.
// ============================================================================
#define ROWB  80                       // bytes per smem row (64 data + 16 pad)
#define AHI_  0
#define ALO_  10240
#define BHI_  20480
#define BLO_  30720
#define BUFB  40960
#define GEMM_SMEM (2 * BUFB)           // 81920

__device__ __forceinline__ void ldmx4(unsigned r[4], unsigned addr) {
    asm volatile("ldmatrix.sync.aligned.m8n8.x4.shared.b16 {%0,%1,%2,%3},[%4];"
                 : "=r"(r[0]), "=r"(r[1]), "=r"(r[2]), "=r"(r[3]) : "r"(addr));
}
__device__ __forceinline__ void mma16816(float c[4], const unsigned a[4],
                                         const unsigned b0, const unsigned b1) {
    asm volatile("mma.sync.aligned.m16n8k16.row.col.f32.bf16.bf16.f32 "
                 "{%0,%1,%2,%3},{%4,%5,%6,%7},{%8,%9},{%0,%1,%2,%3};"
                 : "+f"(c[0]), "+f"(c[1]), "+f"(c[2]), "+f"(c[3])
                 : "r"(a[0]), "r"(a[1]), "r"(a[2]), "r"(a[3]), "r"(b0), "r"(b1));
}
__device__ __forceinline__ void split4(float4 v, uint2& h, uint2& l) {
    __nv_bfloat16 hx = __float2bfloat16(v.x), hy = __float2bfloat16(v.y);
    __nv_bfloat16 hz = __float2bfloat16(v.z), hw = __float2bfloat16(v.w);
    __nv_bfloat16 lx = __float2bfloat16(v.x - __bfloat162float(hx));
    __nv_bfloat16 ly = __float2bfloat16(v.y - __bfloat162float(hy));
    __nv_bfloat16 lz = __float2bfloat16(v.z - __bfloat162float(hz));
    __nv_bfloat16 lw = __float2bfloat16(v.w - __bfloat162float(hw));
    h.x = (unsigned)__bfloat16_as_ushort(hx) | ((unsigned)__bfloat16_as_ushort(hy) << 16);
    h.y = (unsigned)__bfloat16_as_ushort(hz) | ((unsigned)__bfloat16_as_ushort(hw) << 16);
    l.x = (unsigned)__bfloat16_as_ushort(lx) | ((unsigned)__bfloat16_as_ushort(ly) << 16);
    l.y = (unsigned)__bfloat16_as_ushort(lz) | ((unsigned)__bfloat16_as_ushort(lw) << 16);
}

__global__ __launch_bounds__(256) void gemm_bf16s(
    const float* __restrict__ A, const float* __restrict__ B,
    float* __restrict__ C, int N, const float* __restrict__ lam, int lidx)
{
    extern __shared__ __align__(128) char smem[];
    const unsigned sb = (unsigned)__cvta_generic_to_shared(smem);
    const int tid  = threadIdx.x;
    const int wid  = tid >> 5;
    const int lane = tid & 31;
    const int m0 = blockIdx.y * 128;
    const int n0 = blockIdx.x * 128;
    const int wm0 = (wid & 1) * 64;
    const int wn0 = (wid >> 1) * 32;

    const int srow = tid >> 3;        // 0..31 staging row block? no: f>>3 below
    const int sc4  = tid & 7;

    float acc[4][4][4];
#pragma unroll
    for (int mi = 0; mi < 4; mi++)
#pragma unroll
        for (int ni = 0; ni < 4; ni++)
#pragma unroll
            for (int e = 0; e < 4; e++) acc[mi][ni][e] = 0.f;

    // ---- staging: gmem fp32 -> (hi,lo) bf16 -> smem ----
    auto stage = [&](int c, int buf) {
        const int kc = c * 32;
        char* bp = smem + buf * BUFB;
#pragma unroll
        for (int i = 0; i < 4; i++) {
            int f = tid + i * 256;            // 0..1023
            int row = f >> 3;                 // 0..127
            int c4  = f & 7;                  // *4 = k offset
            float4 va = *(const float4*)(A + (size_t)(m0 + row) * 1024 + kc + c4 * 4);
            float4 vb = *(const float4*)(B + (size_t)(n0 + row) * 1024 + kc + c4 * 4);
            uint2 h, l;
            split4(va, h, l);
            *(uint2*)(bp + AHI_ + row * ROWB + c4 * 8) = h;
            *(uint2*)(bp + ALO_ + row * ROWB + c4 * 8) = l;
            split4(vb, h, l);
            *(uint2*)(bp + BHI_ + row * ROWB + c4 * 8) = h;
            *(uint2*)(bp + BLO_ + row * ROWB + c4 * 8) = l;
        }
    };

    // ldmatrix lane geometry
    const int a_row = lane & 15;
    const int a_kb  = (lane >> 4) * 16;
    const int b_nrl = ((lane >> 4) << 3) + (lane & 7);
    const int b_kb  = ((lane >> 3) & 1) * 16;

    stage(0, 0);
    __syncthreads();

    for (int c = 0; c < 32; c++) {
        const int buf = c & 1;
        if (c + 1 < 32) stage(c + 1, buf ^ 1);

        const unsigned base = sb + buf * BUFB;
#pragma unroll
        for (int ks = 0; ks < 2; ks++) {
            unsigned ah[4][4], al[4][4], bh[4][2], bl[4][2];
#pragma unroll
            for (int mi = 0; mi < 4; mi++) {
                unsigned ad = base + AHI_ +
                    (unsigned)((wm0 + mi * 16 + a_row) * ROWB + ks * 32 + a_kb);
                ldmx4(ah[mi], ad);
                ldmx4(al[mi], ad + (ALO_ - AHI_));
            }
#pragma unroll
            for (int p = 0; p < 2; p++) {
                unsigned bd = base + BHI_ +
                    (unsigned)((wn0 + p * 16 + b_nrl) * ROWB + ks * 32 + b_kb);
                unsigned r[4];
                ldmx4(r, bd);
                bh[2*p][0] = r[0]; bh[2*p][1] = r[1];
                bh[2*p+1][0] = r[2]; bh[2*p+1][1] = r[3];
                ldmx4(r, bd + (BLO_ - BHI_));
                bl[2*p][0] = r[0]; bl[2*p][1] = r[1];
                bl[2*p+1][0] = r[2]; bl[2*p+1][1] = r[3];
            }
#pragma unroll
            for (int mi = 0; mi < 4; mi++)
#pragma unroll
                for (int ni = 0; ni < 4; ni++) {
                    mma16816(acc[mi][ni], ah[mi], bh[ni][0], bh[ni][1]);
                    mma16816(acc[mi][ni], al[mi], bh[ni][0], bh[ni][1]);
                    mma16816(acc[mi][ni], ah[mi], bl[ni][0], bl[ni][1]);
                }
        }
        __syncthreads();
    }

    // ---- epilogue ----
    const float alpha = lam[lidx];
    const int r  = lane >> 2;
    const int cc = (lane & 3) * 2;
#pragma unroll
    for (int mi = 0; mi < 4; mi++)
#pragma unroll
        for (int ni = 0; ni < 4; ni++) {
            const int row = m0 + wm0 + mi * 16 + r;
            const int col = n0 + wn0 + ni * 8 + cc;
            float2 w0; w0.x = alpha * acc[mi][ni][0]; w0.y = alpha * acc[mi][ni][1];
            float2 w1; w1.x = alpha * acc[mi][ni][2]; w1.y = alpha * acc[mi][ni][3];
            *(float2*)(C + (size_t)row * N + col) = w0;
            *(float2*)(C + (size_t)(row + 8) * N + col) = w1;
        }
    (void)srow; (void)sc4;
}

// ------------- postprocess: rmsnorm + rotary + gates + ve add --------------
__global__ __launch_bounds__(256) void postproc_kernel(
    const float* __restrict__ x, const float* __restrict__ ve,
    const float* __restrict__ ve_gate_w, const float* __restrict__ attn_gate_w,
    const float* __restrict__ cosb, const float* __restrict__ sinb)
{
    const int t    = blockIdx.x;
    const int w    = threadIdx.x >> 5;
    const int lane = threadIdx.x & 31;
    const float* base = g_qkv + (size_t)t * (3 * DIM_);

    const float c0 = cosb[t * 64 + lane],      s0 = sinb[t * 64 + lane];
    const float c1 = cosb[t * 64 + lane + 32], s1 = sinb[t * 64 + lane + 32];

    {
        const float* qb = base + w * D_;
        float a0 = qb[lane], a1 = qb[lane + 32], a2 = qb[lane + 64], a3 = qb[lane + 96];
        float ss = a0*a0 + a1*a1 + a2*a2 + a3*a3;
#pragma unroll
        for (int off = 16; off; off >>= 1) ss += __shfl_xor_sync(0xffffffffu, ss, off);
        float r = rsqrtf(ss * (1.0f / 128.0f) + 1e-6f);
        a0 *= r; a1 *= r; a2 *= r; a3 *= r;
        float* qp = g_q + (size_t)t * DIM_ + w * D_;
        qp[lane]      =  a0 * c0 + a2 * s0;
        qp[lane + 32] =  a1 * c1 + a3 * s1;
        qp[lane + 64] = -a0 * s0 + a2 * c0;
        qp[lane + 96] = -a1 * s1 + a3 * c1;
    }
    {
        const float* kb = base + DIM_ + w * D_;
        float a0 = kb[lane], a1 = kb[lane + 32], a2 = kb[lane + 64], a3 = kb[lane + 96];
        float ss = a0*a0 + a1*a1 + a2*a2 + a3*a3;
#pragma unroll
        for (int off = 16; off; off >>= 1) ss += __shfl_xor_sync(0xffffffffu, ss, off);
        float r = rsqrtf(ss * (1.0f / 128.0f) + 1e-6f);
        a0 *= r; a1 *= r; a2 *= r; a3 *= r;
        float* kp = g_krot + (size_t)t * DIM_ + w * D_;
        kp[lane]      =  a0 * c0 + a2 * s0;
        kp[lane + 32] =  a1 * c1 + a3 * s1;
        kp[lane + 64] = -a0 * s0 + a2 * c0;
        kp[lane + 96] = -a1 * s1 + a3 * c1;
    }
    float xv = (lane < 16) ? x[(size_t)t * DIM_ + lane] : 0.f;
    float dv = (lane < 16) ? xv * ve_gate_w[w * 16 + lane]   : 0.f;
    float da = (lane < 16) ? xv * attn_gate_w[w * 16 + lane] : 0.f;
#pragma unroll
    for (int off = 16; off; off >>= 1) {
        dv += __shfl_xor_sync(0xffffffffu, dv, off);
        da += __shfl_xor_sync(0xffffffffu, da, off);
    }
    const float veg = 2.0f / (1.0f + __expf(-dv));
    if (lane == 0) g_gate[t * H_ + w] = 1.0f / (1.0f + __expf(-da));
    {
        const float* vb  = base + 2 * DIM_ + w * D_;
        const float* vp2 = ve + (size_t)t * DIM_ + w * D_;
        float* vp = g_v + (size_t)t * DIM_ + w * D_;
        vp[lane]      = vb[lane]      + veg * vp2[lane];
        vp[lane + 32] = vb[lane + 32] + veg * vp2[lane + 32];
        vp[lane + 64] = vb[lane + 64] + veg * vp2[lane + 64];
        vp[lane + 96] = vb[lane + 96] + veg * vp2[lane + 96];
    }
}

// ------------- k-shift: quarters 1,3 come from t-1 -------------------------
__global__ __launch_bounds__(256) void kshift_kernel()
{
    int idx = blockIdx.x * blockDim.x + threadIdx.x;
    int t = idx >> 10;
    int c = idx & 1023;
    int d = c & 127;
    int qtr = d >> 5;
    int st = (qtr == 1 || qtr == 3) ? (t > 0 ? t - 1 : 0) : t;
    g_k[idx] = g_krot[(size_t)st * DIM_ + c];
}

// ------------- flash attention (fp32 scalar, 64x64 tiles) -------------------
#define QSTR 132
#define PSTR 68
#define ATTN_SMEM ((3 * 64 * QSTR + 64 * PSTR) * 4 + 128 * 4)

__device__ __forceinline__ float rmax16(float v) {
#pragma unroll
    for (int off = 8; off; off >>= 1)
        v = fmaxf(v, __shfl_xor_sync(0xffffffffu, v, off, 16));
    return v;
}
__device__ __forceinline__ float rsum16(float v) {
#pragma unroll
    for (int off = 8; off; off >>= 1)
        v += __shfl_xor_sync(0xffffffffu, v, off, 16);
    return v;
}

__global__ __launch_bounds__(256) void attn_kernel(
    const int* __restrict__ seg, const int* __restrict__ bm_ptr)
{
    extern __shared__ float sm[];
    float* Qs = sm;
    float* Ks = Qs + 64 * QSTR;
    float* Vs = Ks + 64 * QSTR;
    float* Ps = Vs + 64 * QSTR;
    int*  qseg = (int*)(Ps + 64 * PSTR);
    int*  kseg = qseg + 64;

    const int h   = blockIdx.y;
    const int m0  = blockIdx.x * 64;
    const int tid = threadIdx.x;
    const int ty  = tid >> 4, tx = tid & 15;
    const int bm  = bm_ptr[0];

#pragma unroll
    for (int i = 0; i < 8; i++) {
        int idx = tid + i * 256;
        int r = idx >> 5, c4 = idx & 31;
        *(float4*)&Qs[r * QSTR + c4 * 4] =
            *(const float4*)&g_q[(size_t)(m0 + r) * DIM_ + h * D_ + c4 * 4];
    }
    if (tid < 64) qseg[tid] = seg[m0 + tid];
    __syncthreads();

    float m_i[4], l_i[4], Oacc[4][8];
#pragma unroll
    for (int i = 0; i < 4; i++) {
        m_i[i] = -1e30f; l_i[i] = 0.f;
#pragma unroll
        for (int j = 0; j < 8; j++) Oacc[i][j] = 0.f;
    }

    const int qs0 = seg[m0], qs1 = seg[m0 + 63];
    int kb_lo = m0 - bm; if (kb_lo < 0) kb_lo = 0; kb_lo >>= 6;
    const int kb_hi = m0 >> 6;

    for (int kb = kb_lo; kb <= kb_hi; kb++) {
        const int s0 = kb * 64;
        const int ks0 = seg[s0], ks1 = seg[s0 + 63];
        if (ks1 < qs0 || ks0 > qs1) continue;

#pragma unroll
        for (int i = 0; i < 8; i++) {
            int idx = tid + i * 256;
            int r = idx >> 5, c4 = idx & 31;
            *(float4*)&Ks[r * QSTR + c4 * 4] =
                *(const float4*)&g_k[(size_t)(s0 + r) * DIM_ + h * D_ + c4 * 4];
            *(float4*)&Vs[r * QSTR + c4 * 4] =
                *(const float4*)&g_v[(size_t)(s0 + r) * DIM_ + h * D_ + c4 * 4];
        }
        if (tid < 64) kseg[tid] = seg[s0 + tid];
        __syncthreads();

        float s_reg[4][4];
#pragma unroll
        for (int i = 0; i < 4; i++)
#pragma unroll
            for (int j = 0; j < 4; j++) s_reg[i][j] = 0.f;

        for (int d4 = 0; d4 < 32; d4++) {
            float4 qa[4], ka[4];
#pragma unroll
            for (int i = 0; i < 4; i++)
                qa[i] = *(const float4*)&Qs[(ty * 4 + i) * QSTR + d4 * 4];
#pragma unroll
            for (int j = 0; j < 4; j++)
                ka[j] = *(const float4*)&Ks[(tx * 4 + j) * QSTR + d4 * 4];
#pragma unroll
            for (int i = 0; i < 4; i++)
#pragma unroll
                for (int j = 0; j < 4; j++) {
                    s_reg[i][j] = fmaf(qa[i].x, ka[j].x, s_reg[i][j]);
                    s_reg[i][j] = fmaf(qa[i].y, ka[j].y, s_reg[i][j]);
                    s_reg[i][j] = fmaf(qa[i].z, ka[j].z, s_reg[i][j]);
                    s_reg[i][j] = fmaf(qa[i].w, ka[j].w, s_reg[i][j]);
                }
        }

#pragma unroll
        for (int i = 0; i < 4; i++) {
            const int tq = m0 + ty * 4 + i;
            const int sq = qseg[ty * 4 + i];
            float rowmax = -1e30f;
#pragma unroll
            for (int j = 0; j < 4; j++) {
                const int tk = s0 + tx * 4 + j;
                bool valid = (tk <= tq) && (tk >= tq - bm) && (kseg[tx * 4 + j] == sq);
                float sv = valid ? s_reg[i][j] * 0.1f : -1e30f;
                s_reg[i][j] = sv;
                rowmax = fmaxf(rowmax, sv);
            }
            rowmax = rmax16(rowmax);
            const float newm  = fmaxf(m_i[i], rowmax);
            const float alpha = __expf(m_i[i] - newm);
            m_i[i] = newm;
            float rs = 0.f;
#pragma unroll
            for (int j = 0; j < 4; j++) {
                float p = __expf(s_reg[i][j] - newm);
                Ps[(ty * 4 + i) * PSTR + tx * 4 + j] = p;
                rs += p;
            }
            rs = rsum16(rs);
            l_i[i] = l_i[i] * alpha + rs;
#pragma unroll
            for (int j = 0; j < 8; j++) Oacc[i][j] *= alpha;
        }
        __syncthreads();

        for (int s = 0; s < 64; s++) {
            float vv[8];
#pragma unroll
            for (int j = 0; j < 8; j++) vv[j] = Vs[s * QSTR + tx + 16 * j];
#pragma unroll
            for (int i = 0; i < 4; i++) {
                float p = Ps[(ty * 4 + i) * PSTR + s];
#pragma unroll
                for (int j = 0; j < 8; j++)
                    Oacc[i][j] = fmaf(p, vv[j], Oacc[i][j]);
            }
        }
        __syncthreads();
    }

#pragma unroll
    for (int i = 0; i < 4; i++) {
        const int tq = m0 + ty * 4 + i;
        const float g = g_gate[tq * H_ + h];
        const float inv = g / l_i[i];
#pragma unroll
        for (int j = 0; j < 8; j++)
            g_y[(size_t)tq * DIM_ + h * D_ + tx + 16 * j] = Oacc[i][j] * inv;
    }
}

// ---------------------------------------------------------------------------
extern "C" void kernel_launch(void* const* d_in, const int* in_sizes, int n_in,
                              void* d_out, int out_size)
{
    const float* x    = (const float*)d_in[0];
    const float* qkvo = (const float*)d_in[1];
    const float* lam  = (const float*)d_in[2];
    const float* ve   = (const float*)d_in[3];
    const float* agw  = (const float*)d_in[4];
    const float* vgw  = (const float*)d_in[5];
    const float* cosb = (const float*)d_in[6];
    const float* sinb = (const float*)d_in[7];
    const int*   seg  = (const int*)d_in[8];
    const int*   bmp  = (const int*)d_in[9];
    float*       out  = (float*)d_out;

    float *p_qkv, *p_y;
    cudaGetSymbolAddress((void**)&p_qkv, g_qkv);
    cudaGetSymbolAddress((void**)&p_y,   g_y);

    cudaFuncSetAttribute(gemm_bf16s,
                         cudaFuncAttributeMaxDynamicSharedMemorySize, GEMM_SMEM);
    cudaFuncSetAttribute(attn_kernel,
                         cudaFuncAttributeMaxDynamicSharedMemorySize, ATTN_SMEM);

    // 1. qkv = lam0 * x @ Wqkv^T   [3072 x 3072]  (tensor cores, bf16-split)
    gemm_bf16s<<<dim3(24, 24), 256, GEMM_SMEM>>>(x, qkvo, p_qkv, 3072, lam, 0);

    // 2. rmsnorm + rotary + gates + ve add
    postproc_kernel<<<T_, 256>>>(x, ve, vgw, agw, cosb, sinb);

    // 3. k quarter-shift
    kshift_kernel<<<(T_ * DIM_) / 256, 256>>>();

    // 4. attention
    attn_kernel<<<dim3(T_ / 64, H_), 256, ATTN_SMEM>>>(seg, bmp);

    // 5. out = lam1 * y @ Wo^T   [3072 x 1024]  (tensor cores, bf16-split)
    gemm_bf16s<<<dim3(8, 24), 256, GEMM_SMEM>>>(p_y, qkvo + 3 * DIM_ * DIM_,
                                                out, 1024, lam, 1);
}

// round 5
// speedup vs baseline: 2.4043x; 1.8056x over previous
#include <cuda_runtime.h>
#include <cuda_bf16.h>
#include <math.h>
#include <stdint.h>

#define T_   3072
#define DIM_ 1024
#define H_   8
#define D_   128

// ---------------- scratch (device globals: no allocation allowed) ----------
__device__ float g_qkv[(size_t)T_ * 3 * DIM_];
__device__ float g_q   [(size_t)T_ * DIM_];
__device__ float g_krot[(size_t)T_ * DIM_];
__device__ float g_k   [(size_t)T_ * DIM_];
__device__ float g_v   [(size_t)T_ * DIM_];
__device__ float g_y   [(size_t)T_ * DIM_];
__device__ float g_gate[T_ * H_];

// ---------------- mma.sync helpers -----------------------------------------
__device__ __forceinline__ void ldmx4(unsigned r[4], unsigned addr) {
    asm volatile("ldmatrix.sync.aligned.m8n8.x4.shared.b16 {%0,%1,%2,%3},[%4];"
                 : "=r"(r[0]), "=r"(r[1]), "=r"(r[2]), "=r"(r[3]) : "r"(addr));
}
__device__ __forceinline__ void ldmx4t(unsigned r[4], unsigned addr) {
    asm volatile("ldmatrix.sync.aligned.m8n8.x4.trans.shared.b16 {%0,%1,%2,%3},[%4];"
                 : "=r"(r[0]), "=r"(r[1]), "=r"(r[2]), "=r"(r[3]) : "r"(addr));
}
__device__ __forceinline__ void mma16816(float c[4], const unsigned a[4],
                                         const unsigned b0, const unsigned b1) {
    asm volatile("mma.sync.aligned.m16n8k16.row.col.f32.bf16.bf16.f32 "
                 "{%0,%1,%2,%3},{%4,%5,%6,%7},{%8,%9},{%0,%1,%2,%3};"
                 : "+f"(c[0]), "+f"(c[1]), "+f"(c[2]), "+f"(c[3])
                 : "r"(a[0]), "r"(a[1]), "r"(a[2]), "r"(a[3]), "r"(b0), "r"(b1));
}
__device__ __forceinline__ void split4(float4 v, uint2& h, uint2& l) {
    __nv_bfloat16 hx = __float2bfloat16(v.x), hy = __float2bfloat16(v.y);
    __nv_bfloat16 hz = __float2bfloat16(v.z), hw = __float2bfloat16(v.w);
    __nv_bfloat16 lx = __float2bfloat16(v.x - __bfloat162float(hx));
    __nv_bfloat16 ly = __float2bfloat16(v.y - __bfloat162float(hy));
    __nv_bfloat16 lz = __float2bfloat16(v.z - __bfloat162float(hz));
    __nv_bfloat16 lw = __float2bfloat16(v.w - __bfloat162float(hw));
    h.x = (unsigned)__bfloat16_as_ushort(hx) | ((unsigned)__bfloat16_as_ushort(hy) << 16);
    h.y = (unsigned)__bfloat16_as_ushort(hz) | ((unsigned)__bfloat16_as_ushort(hw) << 16);
    l.x = (unsigned)__bfloat16_as_ushort(lx) | ((unsigned)__bfloat16_as_ushort(ly) << 16);
    l.y = (unsigned)__bfloat16_as_ushort(lz) | ((unsigned)__bfloat16_as_ushort(lw) << 16);
}
__device__ __forceinline__ unsigned packsplit(float p0, float p1, unsigned& lo) {
    __nv_bfloat16 h0 = __float2bfloat16(p0), h1 = __float2bfloat16(p1);
    __nv_bfloat16 l0 = __float2bfloat16(p0 - __bfloat162float(h0));
    __nv_bfloat16 l1 = __float2bfloat16(p1 - __bfloat162float(h1));
    lo = (unsigned)__bfloat16_as_ushort(l0) | ((unsigned)__bfloat16_as_ushort(l1) << 16);
    return (unsigned)__bfloat16_as_ushort(h0) | ((unsigned)__bfloat16_as_ushort(h1) << 16);
}

// ============================================================================
// bf16-split mma.sync GEMM (unchanged from R4, passing)
// ============================================================================
#define ROWB  80
#define AHI_  0
#define ALO_  10240
#define BHI_  20480
#define BLO_  30720
#define BUFB  40960
#define GEMM_SMEM (2 * BUFB)

__global__ __launch_bounds__(256) void gemm_bf16s(
    const float* __restrict__ A, const float* __restrict__ B,
    float* __restrict__ C, int N, const float* __restrict__ lam, int lidx)
{
    extern __shared__ __align__(128) char smem[];
    const unsigned sb = (unsigned)__cvta_generic_to_shared(smem);
    const int tid  = threadIdx.x;
    const int wid  = tid >> 5;
    const int lane = tid & 31;
    const int m0 = blockIdx.y * 128;
    const int n0 = blockIdx.x * 128;
    const int wm0 = (wid & 1) * 64;
    const int wn0 = (wid >> 1) * 32;

    float acc[4][4][4];
#pragma unroll
    for (int mi = 0; mi < 4; mi++)
#pragma unroll
        for (int ni = 0; ni < 4; ni++)
#pragma unroll
            for (int e = 0; e < 4; e++) acc[mi][ni][e] = 0.f;

    auto stage = [&](int c, int buf) {
        const int kc = c * 32;
        char* bp = smem + buf * BUFB;
#pragma unroll
        for (int i = 0; i < 4; i++) {
            int f = tid + i * 256;
            int row = f >> 3;
            int c4  = f & 7;
            float4 va = *(const float4*)(A + (size_t)(m0 + row) * 1024 + kc + c4 * 4);
            float4 vb = *(const float4*)(B + (size_t)(n0 + row) * 1024 + kc + c4 * 4);
            uint2 h, l;
            split4(va, h, l);
            *(uint2*)(bp + AHI_ + row * ROWB + c4 * 8) = h;
            *(uint2*)(bp + ALO_ + row * ROWB + c4 * 8) = l;
            split4(vb, h, l);
            *(uint2*)(bp + BHI_ + row * ROWB + c4 * 8) = h;
            *(uint2*)(bp + BLO_ + row * ROWB + c4 * 8) = l;
        }
    };

    const int a_row = lane & 15;
    const int a_kb  = (lane >> 4) * 16;
    const int b_nrl = ((lane >> 4) << 3) + (lane & 7);
    const int b_kb  = ((lane >> 3) & 1) * 16;

    stage(0, 0);
    __syncthreads();

    for (int c = 0; c < 32; c++) {
        const int buf = c & 1;
        if (c + 1 < 32) stage(c + 1, buf ^ 1);

        const unsigned base = sb + buf * BUFB;
#pragma unroll
        for (int ks = 0; ks < 2; ks++) {
            unsigned ah[4][4], al[4][4], bh[4][2], bl[4][2];
#pragma unroll
            for (int mi = 0; mi < 4; mi++) {
                unsigned ad = base + AHI_ +
                    (unsigned)((wm0 + mi * 16 + a_row) * ROWB + ks * 32 + a_kb);
                ldmx4(ah[mi], ad);
                ldmx4(al[mi], ad + (ALO_ - AHI_));
            }
#pragma unroll
            for (int p = 0; p < 2; p++) {
                unsigned bd = base + BHI_ +
                    (unsigned)((wn0 + p * 16 + b_nrl) * ROWB + ks * 32 + b_kb);
                unsigned r[4];
                ldmx4(r, bd);
                bh[2*p][0] = r[0]; bh[2*p][1] = r[1];
                bh[2*p+1][0] = r[2]; bh[2*p+1][1] = r[3];
                ldmx4(r, bd + (BLO_ - BHI_));
                bl[2*p][0] = r[0]; bl[2*p][1] = r[1];
                bl[2*p+1][0] = r[2]; bl[2*p+1][1] = r[3];
            }
#pragma unroll
            for (int mi = 0; mi < 4; mi++)
#pragma unroll
                for (int ni = 0; ni < 4; ni++) {
                    mma16816(acc[mi][ni], ah[mi], bh[ni][0], bh[ni][1]);
                    mma16816(acc[mi][ni], al[mi], bh[ni][0], bh[ni][1]);
                    mma16816(acc[mi][ni], ah[mi], bl[ni][0], bl[ni][1]);
                }
        }
        __syncthreads();
    }

    const float alpha = lam[lidx];
    const int r  = lane >> 2;
    const int cc = (lane & 3) * 2;
#pragma unroll
    for (int mi = 0; mi < 4; mi++)
#pragma unroll
        for (int ni = 0; ni < 4; ni++) {
            const int row = m0 + wm0 + mi * 16 + r;
            const int col = n0 + wn0 + ni * 8 + cc;
            float2 w0; w0.x = alpha * acc[mi][ni][0]; w0.y = alpha * acc[mi][ni][1];
            float2 w1; w1.x = alpha * acc[mi][ni][2]; w1.y = alpha * acc[mi][ni][3];
            *(float2*)(C + (size_t)row * N + col) = w0;
            *(float2*)(C + (size_t)(row + 8) * N + col) = w1;
        }
}

// ------------- postprocess: rmsnorm + rotary + gates + ve add --------------
__global__ __launch_bounds__(256) void postproc_kernel(
    const float* __restrict__ x, const float* __restrict__ ve,
    const float* __restrict__ ve_gate_w, const float* __restrict__ attn_gate_w,
    const float* __restrict__ cosb, const float* __restrict__ sinb)
{
    const int t    = blockIdx.x;
    const int w    = threadIdx.x >> 5;
    const int lane = threadIdx.x & 31;
    const float* base = g_qkv + (size_t)t * (3 * DIM_);

    const float c0 = cosb[t * 64 + lane],      s0 = sinb[t * 64 + lane];
    const float c1 = cosb[t * 64 + lane + 32], s1 = sinb[t * 64 + lane + 32];

    {
        const float* qb = base + w * D_;
        float a0 = qb[lane], a1 = qb[lane + 32], a2 = qb[lane + 64], a3 = qb[lane + 96];
        float ss = a0*a0 + a1*a1 + a2*a2 + a3*a3;
#pragma unroll
        for (int off = 16; off; off >>= 1) ss += __shfl_xor_sync(0xffffffffu, ss, off);
        float r = rsqrtf(ss * (1.0f / 128.0f) + 1e-6f);
        a0 *= r; a1 *= r; a2 *= r; a3 *= r;
        float* qp = g_q + (size_t)t * DIM_ + w * D_;
        qp[lane]      =  a0 * c0 + a2 * s0;
        qp[lane + 32] =  a1 * c1 + a3 * s1;
        qp[lane + 64] = -a0 * s0 + a2 * c0;
        qp[lane + 96] = -a1 * s1 + a3 * c1;
    }
    {
        const float* kb = base + DIM_ + w * D_;
        float a0 = kb[lane], a1 = kb[lane + 32], a2 = kb[lane + 64], a3 = kb[lane + 96];
        float ss = a0*a0 + a1*a1 + a2*a2 + a3*a3;
#pragma unroll
        for (int off = 16; off; off >>= 1) ss += __shfl_xor_sync(0xffffffffu, ss, off);
        float r = rsqrtf(ss * (1.0f / 128.0f) + 1e-6f);
        a0 *= r; a1 *= r; a2 *= r; a3 *= r;
        float* kp = g_krot + (size_t)t * DIM_ + w * D_;
        kp[lane]      =  a0 * c0 + a2 * s0;
        kp[lane + 32] =  a1 * c1 + a3 * s1;
        kp[lane + 64] = -a0 * s0 + a2 * c0;
        kp[lane + 96] = -a1 * s1 + a3 * c1;
    }
    float xv = (lane < 16) ? x[(size_t)t * DIM_ + lane] : 0.f;
    float dv = (lane < 16) ? xv * ve_gate_w[w * 16 + lane]   : 0.f;
    float da = (lane < 16) ? xv * attn_gate_w[w * 16 + lane] : 0.f;
#pragma unroll
    for (int off = 16; off; off >>= 1) {
        dv += __shfl_xor_sync(0xffffffffu, dv, off);
        da += __shfl_xor_sync(0xffffffffu, da, off);
    }
    const float veg = 2.0f / (1.0f + __expf(-dv));
    if (lane == 0) g_gate[t * H_ + w] = 1.0f / (1.0f + __expf(-da));
    {
        const float* vb  = base + 2 * DIM_ + w * D_;
        const float* vp2 = ve + (size_t)t * DIM_ + w * D_;
        float* vp = g_v + (size_t)t * DIM_ + w * D_;
        vp[lane]      = vb[lane]      + veg * vp2[lane];
        vp[lane + 32] = vb[lane + 32] + veg * vp2[lane + 32];
        vp[lane + 64] = vb[lane + 64] + veg * vp2[lane + 64];
        vp[lane + 96] = vb[lane + 96] + veg * vp2[lane + 96];
    }
}

// ------------- k-shift: quarters 1,3 come from t-1 -------------------------
__global__ __launch_bounds__(256) void kshift_kernel()
{
    int idx = blockIdx.x * blockDim.x + threadIdx.x;
    int t = idx >> 10;
    int c = idx & 1023;
    int d = c & 127;
    int qtr = d >> 5;
    int st = (qtr == 1 || qtr == 3) ? (t > 0 ? t - 1 : 0) : t;
    g_k[idx] = g_krot[(size_t)st * DIM_ + c];
}

// ============================================================================
// flash attention via mma.sync bf16-split. CTA = (head, 64 q rows), 4 warps.
// ============================================================================
#define KSTR2 136
#define QH_ 0
#define QL_ 8704
#define KH_ 17408
#define KL_ 26112
#define VH_ 34816
#define VL_ 43520
#define ATTN2_SMEM (104448 + 256)

__global__ __launch_bounds__(128) void attn_mma(
    const int* __restrict__ seg, const int* __restrict__ bm_ptr)
{
    extern __shared__ __align__(128) __nv_bfloat16 sm2[];
    int* kseg = (int*)((char*)sm2 + 104448);
    const unsigned sb = (unsigned)__cvta_generic_to_shared(sm2);
    const int h   = blockIdx.y;
    const int m0  = blockIdx.x * 64;
    const int tid = threadIdx.x;
    const int wid = tid >> 5, lane = tid & 31;
    const int bm  = bm_ptr[0];
    const int wr  = wid * 16;

    // stage Q tile (64 x 128) as hi/lo bf16
#pragma unroll
    for (int i = 0; i < 16; i++) {
        int f = tid + i * 128;
        int r = f >> 5, c4 = f & 31;
        float4 v = *(const float4*)&g_q[(size_t)(m0 + r) * DIM_ + h * D_ + c4 * 4];
        uint2 hh, ll;
        split4(v, hh, ll);
        *(uint2*)&sm2[QH_ + r * KSTR2 + c4 * 4] = hh;
        *(uint2*)&sm2[QL_ + r * KSTR2 + c4 * 4] = ll;
    }

    const int r_ = lane >> 2, c_ = lane & 3;
    const int tq0 = m0 + wr + r_, tq1 = tq0 + 8;
    const int sq0 = seg[tq0], sq1 = seg[tq1];

    float mi0 = -1e30f, mi1 = -1e30f, li0 = 0.f, li1 = 0.f;
    float o[16][4];
#pragma unroll
    for (int t = 0; t < 16; t++)
#pragma unroll
        for (int e = 0; e < 4; e++) o[t][e] = 0.f;

    // ldmatrix base addresses
    const unsigned a_addr = sb + (unsigned)(QH_ + (wr + (lane & 15)) * KSTR2 + (lane >> 4) * 8) * 2;
    const int g  = lane >> 3, gl = lane & 7;
    const unsigned kb_addr = sb + (unsigned)(KH_ + ((g >> 1) * 8 + gl) * KSTR2 + (g & 1) * 8) * 2;
    const unsigned vb_addr = sb + (unsigned)(VH_ + ((g & 1) * 8 + gl) * KSTR2 + (g >> 1) * 8) * 2;

    const int qs0 = seg[m0], qs1 = seg[m0 + 63];
    int kb_lo = m0 - bm; if (kb_lo < 0) kb_lo = 0; kb_lo >>= 6;
    const int kb_hi = m0 >> 6;

    for (int kb = kb_lo; kb <= kb_hi; kb++) {
        const int s0 = kb * 64;
        if (seg[s0 + 63] < qs0 || seg[s0] > qs1) continue;

        __syncthreads();   // previous iteration's V reads done before restage
        // stage K (post-shift) and V tiles as hi/lo bf16
#pragma unroll
        for (int i = 0; i < 16; i++) {
            int f = tid + i * 128;
            int r = f >> 5, c4 = f & 31;
            uint2 hh, ll;
            float4 kv = *(const float4*)&g_k[(size_t)(s0 + r) * DIM_ + h * D_ + c4 * 4];
            split4(kv, hh, ll);
            *(uint2*)&sm2[KH_ + r * KSTR2 + c4 * 4] = hh;
            *(uint2*)&sm2[KL_ + r * KSTR2 + c4 * 4] = ll;
            float4 vv = *(const float4*)&g_v[(size_t)(s0 + r) * DIM_ + h * D_ + c4 * 4];
            split4(vv, hh, ll);
            *(uint2*)&sm2[VH_ + r * KSTR2 + c4 * 4] = hh;
            *(uint2*)&sm2[VL_ + r * KSTR2 + c4 * 4] = ll;
        }
        if (tid < 64) kseg[tid] = seg[s0 + tid];
        __syncthreads();

        // ---- S = Q K^T (bf16-split, 3 terms) ----
        float s[8][4];
#pragma unroll
        for (int j = 0; j < 8; j++)
#pragma unroll
            for (int e = 0; e < 4; e++) s[j][e] = 0.f;

#pragma unroll
        for (int kk = 0; kk < 8; kk++) {
            unsigned ah[4], al[4];
            ldmx4(ah, a_addr + kk * 32);
            ldmx4(al, a_addr + (QL_ - QH_) * 2 + kk * 32);
#pragma unroll
            for (int jp = 0; jp < 4; jp++) {
                unsigned bh[4], bl[4];
                unsigned ba = kb_addr + (unsigned)(jp * 16 * KSTR2) * 2 + kk * 32;
                ldmx4(bh, ba);
                ldmx4(bl, ba + (KL_ - KH_) * 2);
                mma16816(s[2*jp],   ah, bh[0], bh[1]);
                mma16816(s[2*jp],   al, bh[0], bh[1]);
                mma16816(s[2*jp],   ah, bl[0], bl[1]);
                mma16816(s[2*jp+1], ah, bh[2], bh[3]);
                mma16816(s[2*jp+1], al, bh[2], bh[3]);
                mma16816(s[2*jp+1], ah, bl[2], bl[3]);
            }
        }

        // ---- mask + online softmax (P stays in registers) ----
        float mx0 = -1e30f, mx1 = -1e30f;
#pragma unroll
        for (int j = 0; j < 8; j++) {
            const int nb = 8 * j + 2 * c_;
            const int tk0 = s0 + nb, tk1 = tk0 + 1;
            const int ka = kseg[nb], kb2 = kseg[nb + 1];
            bool v00 = (tk0 <= tq0) && (tk0 >= tq0 - bm) && (ka  == sq0);
            bool v01 = (tk1 <= tq0) && (tk1 >= tq0 - bm) && (kb2 == sq0);
            bool v10 = (tk0 <= tq1) && (tk0 >= tq1 - bm) && (ka  == sq1);
            bool v11 = (tk1 <= tq1) && (tk1 >= tq1 - bm) && (kb2 == sq1);
            s[j][0] = v00 ? s[j][0] * 0.1f : -1e30f;
            s[j][1] = v01 ? s[j][1] * 0.1f : -1e30f;
            s[j][2] = v10 ? s[j][2] * 0.1f : -1e30f;
            s[j][3] = v11 ? s[j][3] * 0.1f : -1e30f;
            mx0 = fmaxf(mx0, fmaxf(s[j][0], s[j][1]));
            mx1 = fmaxf(mx1, fmaxf(s[j][2], s[j][3]));
        }
        mx0 = fmaxf(mx0, __shfl_xor_sync(0xffffffffu, mx0, 1));
        mx0 = fmaxf(mx0, __shfl_xor_sync(0xffffffffu, mx0, 2));
        mx1 = fmaxf(mx1, __shfl_xor_sync(0xffffffffu, mx1, 1));
        mx1 = fmaxf(mx1, __shfl_xor_sync(0xffffffffu, mx1, 2));

        const float nm0 = fmaxf(mi0, mx0), nm1 = fmaxf(mi1, mx1);
        const float al0 = __expf(mi0 - nm0), al1 = __expf(mi1 - nm1);
        mi0 = nm0; mi1 = nm1;
        float rs0 = 0.f, rs1 = 0.f;
#pragma unroll
        for (int j = 0; j < 8; j++) {
            s[j][0] = __expf(s[j][0] - nm0);
            s[j][1] = __expf(s[j][1] - nm0);
            s[j][2] = __expf(s[j][2] - nm1);
            s[j][3] = __expf(s[j][3] - nm1);
            rs0 += s[j][0] + s[j][1];
            rs1 += s[j][2] + s[j][3];
        }
        rs0 += __shfl_xor_sync(0xffffffffu, rs0, 1);
        rs0 += __shfl_xor_sync(0xffffffffu, rs0, 2);
        rs1 += __shfl_xor_sync(0xffffffffu, rs1, 1);
        rs1 += __shfl_xor_sync(0xffffffffu, rs1, 2);
        li0 = li0 * al0 + rs0;
        li1 = li1 * al1 + rs1;
#pragma unroll
        for (int t = 0; t < 16; t++) {
            o[t][0] *= al0; o[t][1] *= al0;
            o[t][2] *= al1; o[t][3] *= al1;
        }

        // ---- O += P V (P packed from registers, bf16-split 3 terms) ----
#pragma unroll
        for (int ss = 0; ss < 4; ss++) {
            unsigned pha[4], pla[4];
            pha[0] = packsplit(s[2*ss][0],   s[2*ss][1],   pla[0]);
            pha[1] = packsplit(s[2*ss][2],   s[2*ss][3],   pla[1]);
            pha[2] = packsplit(s[2*ss+1][0], s[2*ss+1][1], pla[2]);
            pha[3] = packsplit(s[2*ss+1][2], s[2*ss+1][3], pla[3]);
#pragma unroll
            for (int dp = 0; dp < 8; dp++) {
                unsigned bh[4], bl[4];
                unsigned ba = vb_addr + (unsigned)(ss * 16 * KSTR2) * 2 + dp * 32;
                ldmx4t(bh, ba);
                ldmx4t(bl, ba + (VL_ - VH_) * 2);
                mma16816(o[2*dp],   pha, bh[0], bh[1]);
                mma16816(o[2*dp],   pla, bh[0], bh[1]);
                mma16816(o[2*dp],   pha, bl[0], bl[1]);
                mma16816(o[2*dp+1], pha, bh[2], bh[3]);
                mma16816(o[2*dp+1], pla, bh[2], bh[3]);
                mma16816(o[2*dp+1], pha, bl[2], bl[3]);
            }
        }
    }

    // ---- epilogue: normalize, gate, store ----
    const float gg0 = g_gate[tq0 * H_ + h], gg1 = g_gate[tq1 * H_ + h];
    const float i0 = gg0 / li0, i1 = gg1 / li1;
#pragma unroll
    for (int t = 0; t < 16; t++) {
        float2 w0; w0.x = o[t][0] * i0; w0.y = o[t][1] * i0;
        float2 w1; w1.x = o[t][2] * i1; w1.y = o[t][3] * i1;
        *(float2*)&g_y[(size_t)tq0 * DIM_ + h * D_ + 8 * t + 2 * c_] = w0;
        *(float2*)&g_y[(size_t)tq1 * DIM_ + h * D_ + 8 * t + 2 * c_] = w1;
    }
}

// ---------------------------------------------------------------------------
extern "C" void kernel_launch(void* const* d_in, const int* in_sizes, int n_in,
                              void* d_out, int out_size)
{
    const float* x    = (const float*)d_in[0];
    const float* qkvo = (const float*)d_in[1];
    const float* lam  = (const float*)d_in[2];
    const float* ve   = (const float*)d_in[3];
    const float* agw  = (const float*)d_in[4];
    const float* vgw  = (const float*)d_in[5];
    const float* cosb = (const float*)d_in[6];
    const float* sinb = (const float*)d_in[7];
    const int*   seg  = (const int*)d_in[8];
    const int*   bmp  = (const int*)d_in[9];
    float*       out  = (float*)d_out;

    float *p_qkv, *p_y;
    cudaGetSymbolAddress((void**)&p_qkv, g_qkv);
    cudaGetSymbolAddress((void**)&p_y,   g_y);

    cudaFuncSetAttribute(gemm_bf16s,
                         cudaFuncAttributeMaxDynamicSharedMemorySize, GEMM_SMEM);
    cudaFuncSetAttribute(attn_mma,
                         cudaFuncAttributeMaxDynamicSharedMemorySize, ATTN2_SMEM);

    // 1. qkv = lam0 * x @ Wqkv^T   [3072 x 3072]
    gemm_bf16s<<<dim3(24, 24), 256, GEMM_SMEM>>>(x, qkvo, p_qkv, 3072, lam, 0);

    // 2. rmsnorm + rotary + gates + ve add
    postproc_kernel<<<T_, 256>>>(x, ve, vgw, agw, cosb, sinb);

    // 3. k quarter-shift
    kshift_kernel<<<(T_ * DIM_) / 256, 256>>>();

    // 4. attention (tensor cores)
    attn_mma<<<dim3(T_ / 64, H_), 128, ATTN2_SMEM>>>(seg, bmp);

    // 5. out = lam1 * y @ Wo^T   [3072 x 1024]
    gemm_bf16s<<<dim3(8, 24), 256, GEMM_SMEM>>>(p_y, qkvo + 3 * DIM_ * DIM_,
                                                out, 1024, lam, 1);
}

// round 6
// speedup vs baseline: 3.3025x; 1.3736x over previous
#include <cuda_runtime.h>
#include <cuda_bf16.h>
#include <math.h>
#include <stdint.h>

#define T_   3072
#define DIM_ 1024
#define H_   8
#define D_   128

// ---------------- scratch (device globals: no allocation allowed) ----------
__device__ float g_qkv[(size_t)T_ * 3 * DIM_];
__device__ float g_gate[T_ * H_];
__device__ __nv_bfloat16 g_xh[(size_t)T_ * DIM_], g_xl[(size_t)T_ * DIM_];
__device__ __nv_bfloat16 g_wh[(size_t)4 * DIM_ * DIM_], g_wl[(size_t)4 * DIM_ * DIM_];
__device__ __nv_bfloat16 g_qh[(size_t)T_ * DIM_], g_ql[(size_t)T_ * DIM_];
__device__ __nv_bfloat16 g_kh[(size_t)T_ * DIM_], g_kl[(size_t)T_ * DIM_];
__device__ __nv_bfloat16 g_vh[(size_t)T_ * DIM_], g_vl[(size_t)T_ * DIM_];
__device__ __nv_bfloat16 g_yh[(size_t)T_ * DIM_], g_yl[(size_t)T_ * DIM_];

// ---------------- mma.sync helpers -----------------------------------------
__device__ __forceinline__ void ldmx4(unsigned r[4], unsigned addr) {
    asm volatile("ldmatrix.sync.aligned.m8n8.x4.shared.b16 {%0,%1,%2,%3},[%4];"
                 : "=r"(r[0]), "=r"(r[1]), "=r"(r[2]), "=r"(r[3]) : "r"(addr));
}
__device__ __forceinline__ void ldmx4t(unsigned r[4], unsigned addr) {
    asm volatile("ldmatrix.sync.aligned.m8n8.x4.trans.shared.b16 {%0,%1,%2,%3},[%4];"
                 : "=r"(r[0]), "=r"(r[1]), "=r"(r[2]), "=r"(r[3]) : "r"(addr));
}
__device__ __forceinline__ void mma16816(float c[4], const unsigned a[4],
                                         const unsigned b0, const unsigned b1) {
    asm volatile("mma.sync.aligned.m16n8k16.row.col.f32.bf16.bf16.f32 "
                 "{%0,%1,%2,%3},{%4,%5,%6,%7},{%8,%9},{%0,%1,%2,%3};"
                 : "+f"(c[0]), "+f"(c[1]), "+f"(c[2]), "+f"(c[3])
                 : "r"(a[0]), "r"(a[1]), "r"(a[2]), "r"(a[3]), "r"(b0), "r"(b1));
}
__device__ __forceinline__ void split4(float4 v, uint2& h, uint2& l) {
    __nv_bfloat16 hx = __float2bfloat16(v.x), hy = __float2bfloat16(v.y);
    __nv_bfloat16 hz = __float2bfloat16(v.z), hw = __float2bfloat16(v.w);
    __nv_bfloat16 lx = __float2bfloat16(v.x - __bfloat162float(hx));
    __nv_bfloat16 ly = __float2bfloat16(v.y - __bfloat162float(hy));
    __nv_bfloat16 lz = __float2bfloat16(v.z - __bfloat162float(hz));
    __nv_bfloat16 lw = __float2bfloat16(v.w - __bfloat162float(hw));
    h.x = (unsigned)__bfloat16_as_ushort(hx) | ((unsigned)__bfloat16_as_ushort(hy) << 16);
    h.y = (unsigned)__bfloat16_as_ushort(hz) | ((unsigned)__bfloat16_as_ushort(hw) << 16);
    l.x = (unsigned)__bfloat16_as_ushort(lx) | ((unsigned)__bfloat16_as_ushort(ly) << 16);
    l.y = (unsigned)__bfloat16_as_ushort(lz) | ((unsigned)__bfloat16_as_ushort(lw) << 16);
}
__device__ __forceinline__ unsigned packsplit(float p0, float p1, unsigned& lo) {
    __nv_bfloat16 h0 = __float2bfloat16(p0), h1 = __float2bfloat16(p1);
    __nv_bfloat16 l0 = __float2bfloat16(p0 - __bfloat162float(h0));
    __nv_bfloat16 l1 = __float2bfloat16(p1 - __bfloat162float(h1));
    lo = (unsigned)__bfloat16_as_ushort(l0) | ((unsigned)__bfloat16_as_ushort(l1) << 16);
    return (unsigned)__bfloat16_as_ushort(h0) | ((unsigned)__bfloat16_as_ushort(h1) << 16);
}
__device__ __forceinline__ void store_split(__nv_bfloat16* ph, __nv_bfloat16* pl,
                                            size_t i, float v) {
    __nv_bfloat16 h = __float2bfloat16(v);
    ph[i] = h;
    pl[i] = __float2bfloat16(v - __bfloat162float(h));
}

// ---------------- one-time fp32 -> (hi,lo) bf16 conversion ------------------
__global__ __launch_bounds__(256) void convert_split(
    const float4* __restrict__ src, uint2* __restrict__ dh,
    uint2* __restrict__ dl, int n4)
{
    int i = blockIdx.x * 256 + threadIdx.x;
    if (i < n4) {
        uint2 h, l;
        split4(src[i], h, l);
        dh[i] = h; dl[i] = l;
    }
}

// ============================================================================
// bf16-split mma.sync GEMM reading pre-split planes. Tile 128x128, K-chunk 32.
// ============================================================================
#define ROWB  80
#define AHI_  0
#define ALO_  10240
#define BHI_  20480
#define BLO_  30720
#define BUFB  40960
#define GEMM_SMEM (2 * BUFB)

__global__ __launch_bounds__(256) void gemm_bf16s(
    const __nv_bfloat16* __restrict__ Ah, const __nv_bfloat16* __restrict__ Al,
    const __nv_bfloat16* __restrict__ Bh, const __nv_bfloat16* __restrict__ Bl,
    float* __restrict__ C, int N, const float* __restrict__ lam, int lidx)
{
    extern __shared__ __align__(128) char smem[];
    const unsigned sb = (unsigned)__cvta_generic_to_shared(smem);
    const int tid  = threadIdx.x;
    const int wid  = tid >> 5;
    const int lane = tid & 31;
    const int m0 = blockIdx.y * 128;
    const int n0 = blockIdx.x * 128;
    const int wm0 = (wid & 1) * 64;
    const int wn0 = (wid >> 1) * 32;

    float acc[4][4][4];
#pragma unroll
    for (int mi = 0; mi < 4; mi++)
#pragma unroll
        for (int ni = 0; ni < 4; ni++)
#pragma unroll
            for (int e = 0; e < 4; e++) acc[mi][ni][e] = 0.f;

    // stage: plain uint4 copies from pre-split planes
    auto stage = [&](int c, int buf) {
        const int kc = c * 32;
        char* bp = smem + buf * BUFB;
#pragma unroll
        for (int i = 0; i < 2; i++) {
            int f = tid + i * 256;          // 0..511
            int row = f >> 2, q = f & 3;    // q*8 elements = q*16 bytes
            size_t ga = (size_t)(m0 + row) * 1024 + kc + q * 8;
            size_t gb = (size_t)(n0 + row) * 1024 + kc + q * 8;
            *(uint4*)(bp + AHI_ + row * ROWB + q * 16) = *(const uint4*)(Ah + ga);
            *(uint4*)(bp + ALO_ + row * ROWB + q * 16) = *(const uint4*)(Al + ga);
            *(uint4*)(bp + BHI_ + row * ROWB + q * 16) = *(const uint4*)(Bh + gb);
            *(uint4*)(bp + BLO_ + row * ROWB + q * 16) = *(const uint4*)(Bl + gb);
        }
    };

    const int a_row = lane & 15;
    const int a_kb  = (lane >> 4) * 16;
    const int b_nrl = ((lane >> 4) << 3) + (lane & 7);
    const int b_kb  = ((lane >> 3) & 1) * 16;

    stage(0, 0);
    __syncthreads();

    for (int c = 0; c < 32; c++) {
        const int buf = c & 1;
        if (c + 1 < 32) stage(c + 1, buf ^ 1);

        const unsigned base = sb + buf * BUFB;
#pragma unroll
        for (int ks = 0; ks < 2; ks++) {
            unsigned ah[4][4], al[4][4], bh[4][2], bl[4][2];
#pragma unroll
            for (int mi = 0; mi < 4; mi++) {
                unsigned ad = base + AHI_ +
                    (unsigned)((wm0 + mi * 16 + a_row) * ROWB + ks * 32 + a_kb);
                ldmx4(ah[mi], ad);
                ldmx4(al[mi], ad + (ALO_ - AHI_));
            }
#pragma unroll
            for (int p = 0; p < 2; p++) {
                unsigned bd = base + BHI_ +
                    (unsigned)((wn0 + p * 16 + b_nrl) * ROWB + ks * 32 + b_kb);
                unsigned r[4];
                ldmx4(r, bd);
                bh[2*p][0] = r[0]; bh[2*p][1] = r[1];
                bh[2*p+1][0] = r[2]; bh[2*p+1][1] = r[3];
                ldmx4(r, bd + (BLO_ - BHI_));
                bl[2*p][0] = r[0]; bl[2*p][1] = r[1];
                bl[2*p+1][0] = r[2]; bl[2*p+1][1] = r[3];
            }
#pragma unroll
            for (int mi = 0; mi < 4; mi++)
#pragma unroll
                for (int ni = 0; ni < 4; ni++) {
                    mma16816(acc[mi][ni], ah[mi], bh[ni][0], bh[ni][1]);
                    mma16816(acc[mi][ni], al[mi], bh[ni][0], bh[ni][1]);
                    mma16816(acc[mi][ni], ah[mi], bl[ni][0], bl[ni][1]);
                }
        }
        __syncthreads();
    }

    const float alpha = lam[lidx];
    const int r  = lane >> 2;
    const int cc = (lane & 3) * 2;
#pragma unroll
    for (int mi = 0; mi < 4; mi++)
#pragma unroll
        for (int ni = 0; ni < 4; ni++) {
            const int row = m0 + wm0 + mi * 16 + r;
            const int col = n0 + wn0 + ni * 8 + cc;
            float2 w0; w0.x = alpha * acc[mi][ni][0]; w0.y = alpha * acc[mi][ni][1];
            float2 w1; w1.x = alpha * acc[mi][ni][2]; w1.y = alpha * acc[mi][ni][3];
            *(float2*)(C + (size_t)row * N + col) = w0;
            *(float2*)(C + (size_t)(row + 8) * N + col) = w1;
        }
}

// ------------- postprocess: rmsnorm + rotary + gates + ve; split-bf16 out --
__global__ __launch_bounds__(256) void postproc_kernel(
    const float* __restrict__ x, const float* __restrict__ ve,
    const float* __restrict__ ve_gate_w, const float* __restrict__ attn_gate_w,
    const float* __restrict__ cosb, const float* __restrict__ sinb)
{
    const int t    = blockIdx.x;
    const int w    = threadIdx.x >> 5;
    const int lane = threadIdx.x & 31;
    const float* base = g_qkv + (size_t)t * (3 * DIM_);
    const size_t ob = (size_t)t * DIM_ + w * D_;

    const float c0 = cosb[t * 64 + lane],      s0 = sinb[t * 64 + lane];
    const float c1 = cosb[t * 64 + lane + 32], s1 = sinb[t * 64 + lane + 32];

    {
        const float* qb = base + w * D_;
        float a0 = qb[lane], a1 = qb[lane + 32], a2 = qb[lane + 64], a3 = qb[lane + 96];
        float ss = a0*a0 + a1*a1 + a2*a2 + a3*a3;
#pragma unroll
        for (int off = 16; off; off >>= 1) ss += __shfl_xor_sync(0xffffffffu, ss, off);
        float r = rsqrtf(ss * (1.0f / 128.0f) + 1e-6f);
        a0 *= r; a1 *= r; a2 *= r; a3 *= r;
        store_split(g_qh, g_ql, ob + lane,       a0 * c0 + a2 * s0);
        store_split(g_qh, g_ql, ob + lane + 32,  a1 * c1 + a3 * s1);
        store_split(g_qh, g_ql, ob + lane + 64, -a0 * s0 + a2 * c0);
        store_split(g_qh, g_ql, ob + lane + 96, -a1 * s1 + a3 * c1);
    }
    {
        const float* kb = base + DIM_ + w * D_;
        float a0 = kb[lane], a1 = kb[lane + 32], a2 = kb[lane + 64], a3 = kb[lane + 96];
        float ss = a0*a0 + a1*a1 + a2*a2 + a3*a3;
#pragma unroll
        for (int off = 16; off; off >>= 1) ss += __shfl_xor_sync(0xffffffffu, ss, off);
        float r = rsqrtf(ss * (1.0f / 128.0f) + 1e-6f);
        a0 *= r; a1 *= r; a2 *= r; a3 *= r;
        store_split(g_kh, g_kl, ob + lane,       a0 * c0 + a2 * s0);
        store_split(g_kh, g_kl, ob + lane + 32,  a1 * c1 + a3 * s1);
        store_split(g_kh, g_kl, ob + lane + 64, -a0 * s0 + a2 * c0);
        store_split(g_kh, g_kl, ob + lane + 96, -a1 * s1 + a3 * c1);
    }
    float xv = (lane < 16) ? x[(size_t)t * DIM_ + lane] : 0.f;
    float dv = (lane < 16) ? xv * ve_gate_w[w * 16 + lane]   : 0.f;
    float da = (lane < 16) ? xv * attn_gate_w[w * 16 + lane] : 0.f;
#pragma unroll
    for (int off = 16; off; off >>= 1) {
        dv += __shfl_xor_sync(0xffffffffu, dv, off);
        da += __shfl_xor_sync(0xffffffffu, da, off);
    }
    const float veg = 2.0f / (1.0f + __expf(-dv));
    if (lane == 0) g_gate[t * H_ + w] = 1.0f / (1.0f + __expf(-da));
    {
        const float* vb  = base + 2 * DIM_ + w * D_;
        const float* vp2 = ve + ob;
        store_split(g_vh, g_vl, ob + lane,      vb[lane]      + veg * vp2[lane]);
        store_split(g_vh, g_vl, ob + lane + 32, vb[lane + 32] + veg * vp2[lane + 32]);
        store_split(g_vh, g_vl, ob + lane + 64, vb[lane + 64] + veg * vp2[lane + 64]);
        store_split(g_vh, g_vl, ob + lane + 96, vb[lane + 96] + veg * vp2[lane + 96]);
    }
}

// ============================================================================
// flash attention via mma.sync bf16-split, staged from pre-split planes.
// k quarter-shift fused into K staging. CTA = (head, 64 q rows), 4 warps.
// ============================================================================
#define KSTR2 136
#define QH_ 0
#define QL_ 8704
#define KH_ 17408
#define KL_ 26112
#define VH_ 34816
#define VL_ 43520
#define ATTN2_SMEM (104448 + 256)

__global__ __launch_bounds__(128) void attn_mma(
    const int* __restrict__ seg, const int* __restrict__ bm_ptr)
{
    extern __shared__ __align__(128) __nv_bfloat16 sm2[];
    int* kseg = (int*)((char*)sm2 + 104448);
    const unsigned sb = (unsigned)__cvta_generic_to_shared(sm2);
    const int h   = blockIdx.y;
    const int m0  = blockIdx.x * 64;
    const int tid = threadIdx.x;
    const int wid = tid >> 5, lane = tid & 31;
    const int bm  = bm_ptr[0];
    const int wr  = wid * 16;

    // stage Q tile (64 x 128) hi/lo — plain copies
#pragma unroll
    for (int i = 0; i < 8; i++) {
        int f = tid + i * 128;            // 0..1023 uint4 slots
        int r = f >> 4, u = f & 15;       // u*8 elements
        size_t ga = (size_t)(m0 + r) * DIM_ + h * D_ + u * 8;
        *(uint4*)&sm2[QH_ + r * KSTR2 + u * 8] = *(const uint4*)(g_qh + ga);
        *(uint4*)&sm2[QL_ + r * KSTR2 + u * 8] = *(const uint4*)(g_ql + ga);
    }

    const int r_ = lane >> 2, c_ = lane & 3;
    const int tq0 = m0 + wr + r_, tq1 = tq0 + 8;
    const int sq0 = seg[tq0], sq1 = seg[tq1];

    float mi0 = -1e30f, mi1 = -1e30f, li0 = 0.f, li1 = 0.f;
    float o[16][4];
#pragma unroll
    for (int t = 0; t < 16; t++)
#pragma unroll
        for (int e = 0; e < 4; e++) o[t][e] = 0.f;

    const unsigned a_addr = sb + (unsigned)(QH_ + (wr + (lane & 15)) * KSTR2 + (lane >> 4) * 8) * 2;
    const int g  = lane >> 3, gl = lane & 7;
    const unsigned kb_addr = sb + (unsigned)(KH_ + ((g >> 1) * 8 + gl) * KSTR2 + (g & 1) * 8) * 2;
    const unsigned vb_addr = sb + (unsigned)(VH_ + ((g & 1) * 8 + gl) * KSTR2 + (g >> 1) * 8) * 2;

    const int qs0 = seg[m0], qs1 = seg[m0 + 63];
    int kb_lo = m0 - bm; if (kb_lo < 0) kb_lo = 0; kb_lo >>= 6;
    const int kb_hi = m0 >> 6;

    for (int kb = kb_lo; kb <= kb_hi; kb++) {
        const int s0 = kb * 64;
        if (seg[s0 + 63] < qs0 || seg[s0] > qs1) continue;

        __syncthreads();
        // stage K (fused quarter-shift) + V tiles hi/lo — plain copies
#pragma unroll
        for (int i = 0; i < 8; i++) {
            int f = tid + i * 128;
            int r = f >> 4, u = f & 15;
            int t = s0 + r;
            int ts = ((u >> 2) & 1) ? (t > 0 ? t - 1 : 0) : t;
            size_t gk = (size_t)ts * DIM_ + h * D_ + u * 8;
            size_t gv = (size_t)t  * DIM_ + h * D_ + u * 8;
            *(uint4*)&sm2[KH_ + r * KSTR2 + u * 8] = *(const uint4*)(g_kh + gk);
            *(uint4*)&sm2[KL_ + r * KSTR2 + u * 8] = *(const uint4*)(g_kl + gk);
            *(uint4*)&sm2[VH_ + r * KSTR2 + u * 8] = *(const uint4*)(g_vh + gv);
            *(uint4*)&sm2[VL_ + r * KSTR2 + u * 8] = *(const uint4*)(g_vl + gv);
        }
        if (tid < 64) kseg[tid] = seg[s0 + tid];
        __syncthreads();

        // ---- S = Q K^T (3-term split) ----
        float s[8][4];
#pragma unroll
        for (int j = 0; j < 8; j++)
#pragma unroll
            for (int e = 0; e < 4; e++) s[j][e] = 0.f;

#pragma unroll
        for (int kk = 0; kk < 8; kk++) {
            unsigned ah[4], al[4];
            ldmx4(ah, a_addr + kk * 32);
            ldmx4(al, a_addr + (QL_ - QH_) * 2 + kk * 32);
#pragma unroll
            for (int jp = 0; jp < 4; jp++) {
                unsigned bh[4], bl[4];
                unsigned ba = kb_addr + (unsigned)(jp * 16 * KSTR2) * 2 + kk * 32;
                ldmx4(bh, ba);
                ldmx4(bl, ba + (KL_ - KH_) * 2);
                mma16816(s[2*jp],   ah, bh[0], bh[1]);
                mma16816(s[2*jp],   al, bh[0], bh[1]);
                mma16816(s[2*jp],   ah, bl[0], bl[1]);
                mma16816(s[2*jp+1], ah, bh[2], bh[3]);
                mma16816(s[2*jp+1], al, bh[2], bh[3]);
                mma16816(s[2*jp+1], ah, bl[2], bl[3]);
            }
        }

        // ---- mask + online softmax ----
        float mx0 = -1e30f, mx1 = -1e30f;
#pragma unroll
        for (int j = 0; j < 8; j++) {
            const int nb = 8 * j + 2 * c_;
            const int tk0 = s0 + nb, tk1 = tk0 + 1;
            const int ka = kseg[nb], kb2 = kseg[nb + 1];
            bool v00 = (tk0 <= tq0) && (tk0 >= tq0 - bm) && (ka  == sq0);
            bool v01 = (tk1 <= tq0) && (tk1 >= tq0 - bm) && (kb2 == sq0);
            bool v10 = (tk0 <= tq1) && (tk0 >= tq1 - bm) && (ka  == sq1);
            bool v11 = (tk1 <= tq1) && (tk1 >= tq1 - bm) && (kb2 == sq1);
            s[j][0] = v00 ? s[j][0] * 0.1f : -1e30f;
            s[j][1] = v01 ? s[j][1] * 0.1f : -1e30f;
            s[j][2] = v10 ? s[j][2] * 0.1f : -1e30f;
            s[j][3] = v11 ? s[j][3] * 0.1f : -1e30f;
            mx0 = fmaxf(mx0, fmaxf(s[j][0], s[j][1]));
            mx1 = fmaxf(mx1, fmaxf(s[j][2], s[j][3]));
        }
        mx0 = fmaxf(mx0, __shfl_xor_sync(0xffffffffu, mx0, 1));
        mx0 = fmaxf(mx0, __shfl_xor_sync(0xffffffffu, mx0, 2));
        mx1 = fmaxf(mx1, __shfl_xor_sync(0xffffffffu, mx1, 1));
        mx1 = fmaxf(mx1, __shfl_xor_sync(0xffffffffu, mx1, 2));

        const float nm0 = fmaxf(mi0, mx0), nm1 = fmaxf(mi1, mx1);
        const float al0 = __expf(mi0 - nm0), al1 = __expf(mi1 - nm1);
        mi0 = nm0; mi1 = nm1;
        float rs0 = 0.f, rs1 = 0.f;
#pragma unroll
        for (int j = 0; j < 8; j++) {
            s[j][0] = __expf(s[j][0] - nm0);
            s[j][1] = __expf(s[j][1] - nm0);
            s[j][2] = __expf(s[j][2] - nm1);
            s[j][3] = __expf(s[j][3] - nm1);
            rs0 += s[j][0] + s[j][1];
            rs1 += s[j][2] + s[j][3];
        }
        rs0 += __shfl_xor_sync(0xffffffffu, rs0, 1);
        rs0 += __shfl_xor_sync(0xffffffffu, rs0, 2);
        rs1 += __shfl_xor_sync(0xffffffffu, rs1, 1);
        rs1 += __shfl_xor_sync(0xffffffffu, rs1, 2);
        li0 = li0 * al0 + rs0;
        li1 = li1 * al1 + rs1;
#pragma unroll
        for (int t = 0; t < 16; t++) {
            o[t][0] *= al0; o[t][1] *= al0;
            o[t][2] *= al1; o[t][3] *= al1;
        }

        // ---- O += P V ----
#pragma unroll
        for (int ss = 0; ss < 4; ss++) {
            unsigned pha[4], pla[4];
            pha[0] = packsplit(s[2*ss][0],   s[2*ss][1],   pla[0]);
            pha[1] = packsplit(s[2*ss][2],   s[2*ss][3],   pla[1]);
            pha[2] = packsplit(s[2*ss+1][0], s[2*ss+1][1], pla[2]);
            pha[3] = packsplit(s[2*ss+1][2], s[2*ss+1][3], pla[3]);
#pragma unroll
            for (int dp = 0; dp < 8; dp++) {
                unsigned bh[4], bl[4];
                unsigned ba = vb_addr + (unsigned)(ss * 16 * KSTR2) * 2 + dp * 32;
                ldmx4t(bh, ba);
                ldmx4t(bl, ba + (VL_ - VH_) * 2);
                mma16816(o[2*dp],   pha, bh[0], bh[1]);
                mma16816(o[2*dp],   pla, bh[0], bh[1]);
                mma16816(o[2*dp],   pha, bl[0], bl[1]);
                mma16816(o[2*dp+1], pha, bh[2], bh[3]);
                mma16816(o[2*dp+1], pla, bh[2], bh[3]);
                mma16816(o[2*dp+1], pha, bl[2], bl[3]);
            }
        }
    }

    // ---- epilogue: normalize, gate, store y as hi/lo planes ----
    const float gg0 = g_gate[tq0 * H_ + h], gg1 = g_gate[tq1 * H_ + h];
    const float i0 = gg0 / li0, i1 = gg1 / li1;
#pragma unroll
    for (int t = 0; t < 16; t++) {
        size_t idx0 = (size_t)tq0 * DIM_ + h * D_ + 8 * t + 2 * c_;
        size_t idx1 = (size_t)tq1 * DIM_ + h * D_ + 8 * t + 2 * c_;
        unsigned lw;
        unsigned hw = packsplit(o[t][0] * i0, o[t][1] * i0, lw);
        *(unsigned*)(g_yh + idx0) = hw;
        *(unsigned*)(g_yl + idx0) = lw;
        hw = packsplit(o[t][2] * i1, o[t][3] * i1, lw);
        *(unsigned*)(g_yh + idx1) = hw;
        *(unsigned*)(g_yl + idx1) = lw;
    }
}

// ---------------------------------------------------------------------------
extern "C" void kernel_launch(void* const* d_in, const int* in_sizes, int n_in,
                              void* d_out, int out_size)
{
    const float* x    = (const float*)d_in[0];
    const float* qkvo = (const float*)d_in[1];
    const float* lam  = (const float*)d_in[2];
    const float* ve   = (const float*)d_in[3];
    const float* agw  = (const float*)d_in[4];
    const float* vgw  = (const float*)d_in[5];
    const float* cosb = (const float*)d_in[6];
    const float* sinb = (const float*)d_in[7];
    const int*   seg  = (const int*)d_in[8];
    const int*   bmp  = (const int*)d_in[9];
    float*       out  = (float*)d_out;

    float *p_qkv;
    __nv_bfloat16 *p_xh, *p_xl, *p_wh, *p_wl, *p_yh, *p_yl;
    cudaGetSymbolAddress((void**)&p_qkv, g_qkv);
    cudaGetSymbolAddress((void**)&p_xh, g_xh);
    cudaGetSymbolAddress((void**)&p_xl, g_xl);
    cudaGetSymbolAddress((void**)&p_wh, g_wh);
    cudaGetSymbolAddress((void**)&p_wl, g_wl);
    cudaGetSymbolAddress((void**)&p_yh, g_yh);
    cudaGetSymbolAddress((void**)&p_yl, g_yl);

    cudaFuncSetAttribute(gemm_bf16s,
                         cudaFuncAttributeMaxDynamicSharedMemorySize, GEMM_SMEM);
    cudaFuncSetAttribute(attn_mma,
                         cudaFuncAttributeMaxDynamicSharedMemorySize, ATTN2_SMEM);

    // 0. one-time splits
    convert_split<<<T_ * DIM_ / 1024, 256>>>((const float4*)x,
                                             (uint2*)p_xh, (uint2*)p_xl,
                                             T_ * DIM_ / 4);
    convert_split<<<4 * DIM_ * DIM_ / 1024, 256>>>((const float4*)qkvo,
                                                   (uint2*)p_wh, (uint2*)p_wl,
                                                   4 * DIM_ * DIM_ / 4);

    // 1. qkv = lam0 * x @ Wqkv^T   [3072 x 3072]
    gemm_bf16s<<<dim3(24, 24), 256, GEMM_SMEM>>>(p_xh, p_xl, p_wh, p_wl,
                                                 p_qkv, 3072, lam, 0);

    // 2. rmsnorm + rotary + gates + ve add -> split planes
    postproc_kernel<<<T_, 256>>>(x, ve, vgw, agw, cosb, sinb);

    // 3. attention (tensor cores; k-shift fused)
    attn_mma<<<dim3(T_ / 64, H_), 128, ATTN2_SMEM>>>(seg, bmp);

    // 4. out = lam1 * y @ Wo^T   [3072 x 1024]
    gemm_bf16s<<<dim3(8, 24), 256, GEMM_SMEM>>>(
        p_yh, p_yl, p_wh + (size_t)3 * DIM_ * DIM_, p_wl + (size_t)3 * DIM_ * DIM_,
        out, 1024, lam, 1);
}

// round 7
// speedup vs baseline: 3.3496x; 1.0143x over previous
#include <cuda_runtime.h>
#include <cuda_bf16.h>
#include <math.h>
#include <stdint.h>

#define T_   3072
#define DIM_ 1024
#define H_   8
#define D_   128

// ---------------- scratch (device globals: no allocation allowed) ----------
__device__ float g_qkv[(size_t)T_ * 3 * DIM_];
__device__ float g_gate[T_ * H_];
__device__ __nv_bfloat16 g_xh[(size_t)T_ * DIM_], g_xl[(size_t)T_ * DIM_];
__device__ __nv_bfloat16 g_wh[(size_t)4 * DIM_ * DIM_], g_wl[(size_t)4 * DIM_ * DIM_];
__device__ __nv_bfloat16 g_qh[(size_t)T_ * DIM_], g_ql[(size_t)T_ * DIM_];
__device__ __nv_bfloat16 g_kh[(size_t)T_ * DIM_], g_kl[(size_t)T_ * DIM_];
__device__ __nv_bfloat16 g_vh[(size_t)T_ * DIM_], g_vl[(size_t)T_ * DIM_];
__device__ __nv_bfloat16 g_yh[(size_t)T_ * DIM_], g_yl[(size_t)T_ * DIM_];

// ---------------- helpers ---------------------------------------------------
__device__ __forceinline__ void cpa16(unsigned dst, const void* src) {
    asm volatile("cp.async.cg.shared.global [%0],[%1],16;" :: "r"(dst), "l"(src));
}
#define CP_COMMIT() asm volatile("cp.async.commit_group;" ::: "memory")
#define CP_WAIT0()  asm volatile("cp.async.wait_group 0;" ::: "memory")

__device__ __forceinline__ void ldmx4(unsigned r[4], unsigned addr) {
    asm volatile("ldmatrix.sync.aligned.m8n8.x4.shared.b16 {%0,%1,%2,%3},[%4];"
                 : "=r"(r[0]), "=r"(r[1]), "=r"(r[2]), "=r"(r[3]) : "r"(addr));
}
__device__ __forceinline__ void ldmx4t(unsigned r[4], unsigned addr) {
    asm volatile("ldmatrix.sync.aligned.m8n8.x4.trans.shared.b16 {%0,%1,%2,%3},[%4];"
                 : "=r"(r[0]), "=r"(r[1]), "=r"(r[2]), "=r"(r[3]) : "r"(addr));
}
__device__ __forceinline__ void mma16816(float c[4], const unsigned a[4],
                                         const unsigned b0, const unsigned b1) {
    asm volatile("mma.sync.aligned.m16n8k16.row.col.f32.bf16.bf16.f32 "
                 "{%0,%1,%2,%3},{%4,%5,%6,%7},{%8,%9},{%0,%1,%2,%3};"
                 : "+f"(c[0]), "+f"(c[1]), "+f"(c[2]), "+f"(c[3])
                 : "r"(a[0]), "r"(a[1]), "r"(a[2]), "r"(a[3]), "r"(b0), "r"(b1));
}
__device__ __forceinline__ void split4(float4 v, uint2& h, uint2& l) {
    __nv_bfloat16 hx = __float2bfloat16(v.x), hy = __float2bfloat16(v.y);
    __nv_bfloat16 hz = __float2bfloat16(v.z), hw = __float2bfloat16(v.w);
    __nv_bfloat16 lx = __float2bfloat16(v.x - __bfloat162float(hx));
    __nv_bfloat16 ly = __float2bfloat16(v.y - __bfloat162float(hy));
    __nv_bfloat16 lz = __float2bfloat16(v.z - __bfloat162float(hz));
    __nv_bfloat16 lw = __float2bfloat16(v.w - __bfloat162float(hw));
    h.x = (unsigned)__bfloat16_as_ushort(hx) | ((unsigned)__bfloat16_as_ushort(hy) << 16);
    h.y = (unsigned)__bfloat16_as_ushort(hz) | ((unsigned)__bfloat16_as_ushort(hw) << 16);
    l.x = (unsigned)__bfloat16_as_ushort(lx) | ((unsigned)__bfloat16_as_ushort(ly) << 16);
    l.y = (unsigned)__bfloat16_as_ushort(lz) | ((unsigned)__bfloat16_as_ushort(lw) << 16);
}
__device__ __forceinline__ unsigned packsplit(float p0, float p1, unsigned& lo) {
    __nv_bfloat16 h0 = __float2bfloat16(p0), h1 = __float2bfloat16(p1);
    __nv_bfloat16 l0 = __float2bfloat16(p0 - __bfloat162float(h0));
    __nv_bfloat16 l1 = __float2bfloat16(p1 - __bfloat162float(h1));
    lo = (unsigned)__bfloat16_as_ushort(l0) | ((unsigned)__bfloat16_as_ushort(l1) << 16);
    return (unsigned)__bfloat16_as_ushort(h0) | ((unsigned)__bfloat16_as_ushort(h1) << 16);
}
__device__ __forceinline__ void store_split(__nv_bfloat16* ph, __nv_bfloat16* pl,
                                            size_t i, float v) {
    __nv_bfloat16 h = __float2bfloat16(v);
    ph[i] = h;
    pl[i] = __float2bfloat16(v - __bfloat162float(h));
}

// ---------------- one-time fp32 -> (hi,lo) bf16 conversion ------------------
__global__ __launch_bounds__(256) void convert_split(
    const float4* __restrict__ src, uint2* __restrict__ dh,
    uint2* __restrict__ dl, int n4)
{
    int i = blockIdx.x * 256 + threadIdx.x;
    if (i < n4) {
        uint2 h, l;
        split4(src[i], h, l);
        dh[i] = h; dl[i] = l;
    }
}

// ============================================================================
// bf16-split mma.sync GEMM, cp.async staging with load/compute overlap.
// ============================================================================
#define ROWB  80
#define AHI_  0
#define ALO_  10240
#define BHI_  20480
#define BLO_  30720
#define BUFB  40960
#define GEMM_SMEM (2 * BUFB)

__global__ __launch_bounds__(256) void gemm_bf16s(
    const __nv_bfloat16* __restrict__ Ah, const __nv_bfloat16* __restrict__ Al,
    const __nv_bfloat16* __restrict__ Bh, const __nv_bfloat16* __restrict__ Bl,
    float* __restrict__ C, int N, const float* __restrict__ lam, int lidx)
{
    extern __shared__ __align__(128) char smem[];
    const unsigned sb = (unsigned)__cvta_generic_to_shared(smem);
    const int tid  = threadIdx.x;
    const int wid  = tid >> 5;
    const int lane = tid & 31;
    const int m0 = blockIdx.y * 128;
    const int n0 = blockIdx.x * 128;
    const int wm0 = (wid & 1) * 64;
    const int wn0 = (wid >> 1) * 32;

    float acc[4][4][4];
#pragma unroll
    for (int mi = 0; mi < 4; mi++)
#pragma unroll
        for (int ni = 0; ni < 4; ni++)
#pragma unroll
            for (int e = 0; e < 4; e++) acc[mi][ni][e] = 0.f;

    auto stage = [&](int c, int buf) {
        const int kc = c * 32;
        const unsigned bb = sb + buf * BUFB;
#pragma unroll
        for (int i = 0; i < 2; i++) {
            int f = tid + i * 256;
            int row = f >> 2, q = f & 3;
            size_t ga = (size_t)(m0 + row) * 1024 + kc + q * 8;
            size_t gb = (size_t)(n0 + row) * 1024 + kc + q * 8;
            unsigned so = (unsigned)(row * ROWB + q * 16);
            cpa16(bb + AHI_ + so, Ah + ga);
            cpa16(bb + ALO_ + so, Al + ga);
            cpa16(bb + BHI_ + so, Bh + gb);
            cpa16(bb + BLO_ + so, Bl + gb);
        }
        CP_COMMIT();
    };

    const int a_row = lane & 15;
    const int a_kb  = (lane >> 4) * 16;
    const int b_nrl = ((lane >> 4) << 3) + (lane & 7);
    const int b_kb  = ((lane >> 3) & 1) * 16;

    stage(0, 0);

    for (int c = 0; c < 32; c++) {
        const int buf = c & 1;
        CP_WAIT0();
        __syncthreads();
        if (c + 1 < 32) stage(c + 1, buf ^ 1);   // streams in during compute

        const unsigned base = sb + buf * BUFB;
#pragma unroll
        for (int ks = 0; ks < 2; ks++) {
            unsigned ah[4][4], al[4][4], bh[4][2], bl[4][2];
#pragma unroll
            for (int mi = 0; mi < 4; mi++) {
                unsigned ad = base + AHI_ +
                    (unsigned)((wm0 + mi * 16 + a_row) * ROWB + ks * 32 + a_kb);
                ldmx4(ah[mi], ad);
                ldmx4(al[mi], ad + (ALO_ - AHI_));
            }
#pragma unroll
            for (int p = 0; p < 2; p++) {
                unsigned bd = base + BHI_ +
                    (unsigned)((wn0 + p * 16 + b_nrl) * ROWB + ks * 32 + b_kb);
                unsigned r[4];
                ldmx4(r, bd);
                bh[2*p][0] = r[0]; bh[2*p][1] = r[1];
                bh[2*p+1][0] = r[2]; bh[2*p+1][1] = r[3];
                ldmx4(r, bd + (BLO_ - BHI_));
                bl[2*p][0] = r[0]; bl[2*p][1] = r[1];
                bl[2*p+1][0] = r[2]; bl[2*p+1][1] = r[3];
            }
#pragma unroll
            for (int mi = 0; mi < 4; mi++)
#pragma unroll
                for (int ni = 0; ni < 4; ni++) {
                    mma16816(acc[mi][ni], ah[mi], bh[ni][0], bh[ni][1]);
                    mma16816(acc[mi][ni], al[mi], bh[ni][0], bh[ni][1]);
                    mma16816(acc[mi][ni], ah[mi], bl[ni][0], bl[ni][1]);
                }
        }
    }

    const float alpha = lam[lidx];
    const int r  = lane >> 2;
    const int cc = (lane & 3) * 2;
#pragma unroll
    for (int mi = 0; mi < 4; mi++)
#pragma unroll
        for (int ni = 0; ni < 4; ni++) {
            const int row = m0 + wm0 + mi * 16 + r;
            const int col = n0 + wn0 + ni * 8 + cc;
            float2 w0; w0.x = alpha * acc[mi][ni][0]; w0.y = alpha * acc[mi][ni][1];
            float2 w1; w1.x = alpha * acc[mi][ni][2]; w1.y = alpha * acc[mi][ni][3];
            *(float2*)(C + (size_t)row * N + col) = w0;
            *(float2*)(C + (size_t)(row + 8) * N + col) = w1;
        }
}

// ------------- postprocess: rmsnorm + rotary + gates + ve; split-bf16 out --
__global__ __launch_bounds__(256) void postproc_kernel(
    const float* __restrict__ x, const float* __restrict__ ve,
    const float* __restrict__ ve_gate_w, const float* __restrict__ attn_gate_w,
    const float* __restrict__ cosb, const float* __restrict__ sinb)
{
    const int t    = blockIdx.x;
    const int w    = threadIdx.x >> 5;
    const int lane = threadIdx.x & 31;
    const float* base = g_qkv + (size_t)t * (3 * DIM_);
    const size_t ob = (size_t)t * DIM_ + w * D_;

    const float c0 = cosb[t * 64 + lane],      s0 = sinb[t * 64 + lane];
    const float c1 = cosb[t * 64 + lane + 32], s1 = sinb[t * 64 + lane + 32];

    {
        const float* qb = base + w * D_;
        float a0 = qb[lane], a1 = qb[lane + 32], a2 = qb[lane + 64], a3 = qb[lane + 96];
        float ss = a0*a0 + a1*a1 + a2*a2 + a3*a3;
#pragma unroll
        for (int off = 16; off; off >>= 1) ss += __shfl_xor_sync(0xffffffffu, ss, off);
        float r = rsqrtf(ss * (1.0f / 128.0f) + 1e-6f);
        a0 *= r; a1 *= r; a2 *= r; a3 *= r;
        store_split(g_qh, g_ql, ob + lane,       a0 * c0 + a2 * s0);
        store_split(g_qh, g_ql, ob + lane + 32,  a1 * c1 + a3 * s1);
        store_split(g_qh, g_ql, ob + lane + 64, -a0 * s0 + a2 * c0);
        store_split(g_qh, g_ql, ob + lane + 96, -a1 * s1 + a3 * c1);
    }
    {
        const float* kb = base + DIM_ + w * D_;
        float a0 = kb[lane], a1 = kb[lane + 32], a2 = kb[lane + 64], a3 = kb[lane + 96];
        float ss = a0*a0 + a1*a1 + a2*a2 + a3*a3;
#pragma unroll
        for (int off = 16; off; off >>= 1) ss += __shfl_xor_sync(0xffffffffu, ss, off);
        float r = rsqrtf(ss * (1.0f / 128.0f) + 1e-6f);
        a0 *= r; a1 *= r; a2 *= r; a3 *= r;
        store_split(g_kh, g_kl, ob + lane,       a0 * c0 + a2 * s0);
        store_split(g_kh, g_kl, ob + lane + 32,  a1 * c1 + a3 * s1);
        store_split(g_kh, g_kl, ob + lane + 64, -a0 * s0 + a2 * c0);
        store_split(g_kh, g_kl, ob + lane + 96, -a1 * s1 + a3 * c1);
    }
    float xv = (lane < 16) ? x[(size_t)t * DIM_ + lane] : 0.f;
    float dv = (lane < 16) ? xv * ve_gate_w[w * 16 + lane]   : 0.f;
    float da = (lane < 16) ? xv * attn_gate_w[w * 16 + lane] : 0.f;
#pragma unroll
    for (int off = 16; off; off >>= 1) {
        dv += __shfl_xor_sync(0xffffffffu, dv, off);
        da += __shfl_xor_sync(0xffffffffu, da, off);
    }
    const float veg = 2.0f / (1.0f + __expf(-dv));
    if (lane == 0) g_gate[t * H_ + w] = 1.0f / (1.0f + __expf(-da));
    {
        const float* vb  = base + 2 * DIM_ + w * D_;
        const float* vp2 = ve + ob;
        store_split(g_vh, g_vl, ob + lane,      vb[lane]      + veg * vp2[lane]);
        store_split(g_vh, g_vl, ob + lane + 32, vb[lane + 32] + veg * vp2[lane + 32]);
        store_split(g_vh, g_vl, ob + lane + 64, vb[lane + 64] + veg * vp2[lane + 64]);
        store_split(g_vh, g_vl, ob + lane + 96, vb[lane + 96] + veg * vp2[lane + 96]);
    }
}

// ============================================================================
// flash attention, cp.async staging, heavy-tiles-first ordering.
// ============================================================================
#define KSTR2 136
#define QH_ 0
#define QL_ 8704
#define KH_ 17408
#define KL_ 26112
#define VH_ 34816
#define VL_ 43520
#define ATTN2_SMEM (104448 + 256)

__global__ __launch_bounds__(128) void attn_mma(
    const int* __restrict__ seg, const int* __restrict__ bm_ptr)
{
    extern __shared__ __align__(128) __nv_bfloat16 sm2[];
    int* kseg = (int*)((char*)sm2 + 104448);
    const unsigned sb = (unsigned)__cvta_generic_to_shared(sm2);
    const int h   = blockIdx.y;
    const int m0  = ((int)gridDim.x - 1 - (int)blockIdx.x) * 64;  // heavy first
    const int tid = threadIdx.x;
    const int wid = tid >> 5, lane = tid & 31;
    const int bm  = bm_ptr[0];
    const int wr  = wid * 16;

    // stage Q tile hi/lo via cp.async
#pragma unroll
    for (int i = 0; i < 8; i++) {
        int f = tid + i * 128;
        int r = f >> 4, u = f & 15;
        size_t ga = (size_t)(m0 + r) * DIM_ + h * D_ + u * 8;
        cpa16(sb + (unsigned)(QH_ + r * KSTR2 + u * 8) * 2, g_qh + ga);
        cpa16(sb + (unsigned)(QL_ + r * KSTR2 + u * 8) * 2, g_ql + ga);
    }
    CP_COMMIT();

    const int r_ = lane >> 2, c_ = lane & 3;
    const int tq0 = m0 + wr + r_, tq1 = tq0 + 8;
    const int sq0 = seg[tq0], sq1 = seg[tq1];

    float mi0 = -1e30f, mi1 = -1e30f, li0 = 0.f, li1 = 0.f;
    float o[16][4];
#pragma unroll
    for (int t = 0; t < 16; t++)
#pragma unroll
        for (int e = 0; e < 4; e++) o[t][e] = 0.f;

    const unsigned a_addr = sb + (unsigned)(QH_ + (wr + (lane & 15)) * KSTR2 + (lane >> 4) * 8) * 2;
    const int g  = lane >> 3, gl = lane & 7;
    const unsigned kb_addr = sb + (unsigned)(KH_ + ((g >> 1) * 8 + gl) * KSTR2 + (g & 1) * 8) * 2;
    const unsigned vb_addr = sb + (unsigned)(VH_ + ((g & 1) * 8 + gl) * KSTR2 + (g >> 1) * 8) * 2;

    const int qs0 = seg[m0], qs1 = seg[m0 + 63];
    int kb_lo = m0 - bm; if (kb_lo < 0) kb_lo = 0; kb_lo >>= 6;
    const int kb_hi = m0 >> 6;

    for (int kb = kb_lo; kb <= kb_hi; kb++) {
        const int s0 = kb * 64;
        if (seg[s0 + 63] < qs0 || seg[s0] > qs1) continue;

        __syncthreads();   // prior V readers done before restage
#pragma unroll
        for (int i = 0; i < 8; i++) {
            int f = tid + i * 128;
            int r = f >> 4, u = f & 15;
            int t = s0 + r;
            int ts = ((u >> 2) & 1) ? (t > 0 ? t - 1 : 0) : t;
            size_t gk = (size_t)ts * DIM_ + h * D_ + u * 8;
            size_t gv = (size_t)t  * DIM_ + h * D_ + u * 8;
            cpa16(sb + (unsigned)(KH_ + r * KSTR2 + u * 8) * 2, g_kh + gk);
            cpa16(sb + (unsigned)(KL_ + r * KSTR2 + u * 8) * 2, g_kl + gk);
            cpa16(sb + (unsigned)(VH_ + r * KSTR2 + u * 8) * 2, g_vh + gv);
            cpa16(sb + (unsigned)(VL_ + r * KSTR2 + u * 8) * 2, g_vl + gv);
        }
        CP_COMMIT();
        if (tid < 64) kseg[tid] = seg[s0 + tid];
        CP_WAIT0();
        __syncthreads();

        // ---- S = Q K^T (3-term split) ----
        float s[8][4];
#pragma unroll
        for (int j = 0; j < 8; j++)
#pragma unroll
            for (int e = 0; e < 4; e++) s[j][e] = 0.f;

#pragma unroll
        for (int kk = 0; kk < 8; kk++) {
            unsigned ah[4], al[4];
            ldmx4(ah, a_addr + kk * 32);
            ldmx4(al, a_addr + (QL_ - QH_) * 2 + kk * 32);
#pragma unroll
            for (int jp = 0; jp < 4; jp++) {
                unsigned bh[4], bl[4];
                unsigned ba = kb_addr + (unsigned)(jp * 16 * KSTR2) * 2 + kk * 32;
                ldmx4(bh, ba);
                ldmx4(bl, ba + (KL_ - KH_) * 2);
                mma16816(s[2*jp],   ah, bh[0], bh[1]);
                mma16816(s[2*jp],   al, bh[0], bh[1]);
                mma16816(s[2*jp],   ah, bl[0], bl[1]);
                mma16816(s[2*jp+1], ah, bh[2], bh[3]);
                mma16816(s[2*jp+1], al, bh[2], bh[3]);
                mma16816(s[2*jp+1], ah, bl[2], bl[3]);
            }
        }

        // ---- mask + online softmax ----
        float mx0 = -1e30f, mx1 = -1e30f;
#pragma unroll
        for (int j = 0; j < 8; j++) {
            const int nb = 8 * j + 2 * c_;
            const int tk0 = s0 + nb, tk1 = tk0 + 1;
            const int ka = kseg[nb], kb2 = kseg[nb + 1];
            bool v00 = (tk0 <= tq0) && (tk0 >= tq0 - bm) && (ka  == sq0);
            bool v01 = (tk1 <= tq0) && (tk1 >= tq0 - bm) && (kb2 == sq0);
            bool v10 = (tk0 <= tq1) && (tk0 >= tq1 - bm) && (ka  == sq1);
            bool v11 = (tk1 <= tq1) && (tk1 >= tq1 - bm) && (kb2 == sq1);
            s[j][0] = v00 ? s[j][0] * 0.1f : -1e30f;
            s[j][1] = v01 ? s[j][1] * 0.1f : -1e30f;
            s[j][2] = v10 ? s[j][2] * 0.1f : -1e30f;
            s[j][3] = v11 ? s[j][3] * 0.1f : -1e30f;
            mx0 = fmaxf(mx0, fmaxf(s[j][0], s[j][1]));
            mx1 = fmaxf(mx1, fmaxf(s[j][2], s[j][3]));
        }
        mx0 = fmaxf(mx0, __shfl_xor_sync(0xffffffffu, mx0, 1));
        mx0 = fmaxf(mx0, __shfl_xor_sync(0xffffffffu, mx0, 2));
        mx1 = fmaxf(mx1, __shfl_xor_sync(0xffffffffu, mx1, 1));
        mx1 = fmaxf(mx1, __shfl_xor_sync(0xffffffffu, mx1, 2));

        const float nm0 = fmaxf(mi0, mx0), nm1 = fmaxf(mi1, mx1);
        const float al0 = __expf(mi0 - nm0), al1 = __expf(mi1 - nm1);
        mi0 = nm0; mi1 = nm1;
        float rs0 = 0.f, rs1 = 0.f;
#pragma unroll
        for (int j = 0; j < 8; j++) {
            s[j][0] = __expf(s[j][0] - nm0);
            s[j][1] = __expf(s[j][1] - nm0);
            s[j][2] = __expf(s[j][2] - nm1);
            s[j][3] = __expf(s[j][3] - nm1);
            rs0 += s[j][0] + s[j][1];
            rs1 += s[j][2] + s[j][3];
        }
        rs0 += __shfl_xor_sync(0xffffffffu, rs0, 1);
        rs0 += __shfl_xor_sync(0xffffffffu, rs0, 2);
        rs1 += __shfl_xor_sync(0xffffffffu, rs1, 1);
        rs1 += __shfl_xor_sync(0xffffffffu, rs1, 2);
        li0 = li0 * al0 + rs0;
        li1 = li1 * al1 + rs1;
#pragma unroll
        for (int t = 0; t < 16; t++) {
            o[t][0] *= al0; o[t][1] *= al0;
            o[t][2] *= al1; o[t][3] *= al1;
        }

        // ---- O += P V ----
#pragma unroll
        for (int ss = 0; ss < 4; ss++) {
            unsigned pha[4], pla[4];
            pha[0] = packsplit(s[2*ss][0],   s[2*ss][1],   pla[0]);
            pha[1] = packsplit(s[2*ss][2],   s[2*ss][3],   pla[1]);
            pha[2] = packsplit(s[2*ss+1][0], s[2*ss+1][1], pla[2]);
            pha[3] = packsplit(s[2*ss+1][2], s[2*ss+1][3], pla[3]);
#pragma unroll
            for (int dp = 0; dp < 8; dp++) {
                unsigned bh[4], bl[4];
                unsigned ba = vb_addr + (unsigned)(ss * 16 * KSTR2) * 2 + dp * 32;
                ldmx4t(bh, ba);
                ldmx4t(bl, ba + (VL_ - VH_) * 2);
                mma16816(o[2*dp],   pha, bh[0], bh[1]);
                mma16816(o[2*dp],   pla, bh[0], bh[1]);
                mma16816(o[2*dp],   pha, bl[0], bl[1]);
                mma16816(o[2*dp+1], pha, bh[2], bh[3]);
                mma16816(o[2*dp+1], pla, bh[2], bh[3]);
                mma16816(o[2*dp+1], pha, bl[2], bl[3]);
            }
        }
    }

    // ---- epilogue ----
    const float gg0 = g_gate[tq0 * H_ + h], gg1 = g_gate[tq1 * H_ + h];
    const float i0 = gg0 / li0, i1 = gg1 / li1;
#pragma unroll
    for (int t = 0; t < 16; t++) {
        size_t idx0 = (size_t)tq0 * DIM_ + h * D_ + 8 * t + 2 * c_;
        size_t idx1 = (size_t)tq1 * DIM_ + h * D_ + 8 * t + 2 * c_;
        unsigned lw;
        unsigned hw = packsplit(o[t][0] * i0, o[t][1] * i0, lw);
        *(unsigned*)(g_yh + idx0) = hw;
        *(unsigned*)(g_yl + idx0) = lw;
        hw = packsplit(o[t][2] * i1, o[t][3] * i1, lw);
        *(unsigned*)(g_yh + idx1) = hw;
        *(unsigned*)(g_yl + idx1) = lw;
    }
}

// ---------------------------------------------------------------------------
extern "C" void kernel_launch(void* const* d_in, const int* in_sizes, int n_in,
                              void* d_out, int out_size)
{
    const float* x    = (const float*)d_in[0];
    const float* qkvo = (const float*)d_in[1];
    const float* lam  = (const float*)d_in[2];
    const float* ve   = (const float*)d_in[3];
    const float* agw  = (const float*)d_in[4];
    const float* vgw  = (const float*)d_in[5];
    const float* cosb = (const float*)d_in[6];
    const float* sinb = (const float*)d_in[7];
    const int*   seg  = (const int*)d_in[8];
    const int*   bmp  = (const int*)d_in[9];
    float*       out  = (float*)d_out;

    float *p_qkv;
    __nv_bfloat16 *p_xh, *p_xl, *p_wh, *p_wl, *p_yh, *p_yl;
    cudaGetSymbolAddress((void**)&p_qkv, g_qkv);
    cudaGetSymbolAddress((void**)&p_xh, g_xh);
    cudaGetSymbolAddress((void**)&p_xl, g_xl);
    cudaGetSymbolAddress((void**)&p_wh, g_wh);
    cudaGetSymbolAddress((void**)&p_wl, g_wl);
    cudaGetSymbolAddress((void**)&p_yh, g_yh);
    cudaGetSymbolAddress((void**)&p_yl, g_yl);

    cudaFuncSetAttribute(gemm_bf16s,
                         cudaFuncAttributeMaxDynamicSharedMemorySize, GEMM_SMEM);
    cudaFuncSetAttribute(attn_mma,
                         cudaFuncAttributeMaxDynamicSharedMemorySize, ATTN2_SMEM);

    // 0. one-time splits
    convert_split<<<T_ * DIM_ / 1024, 256>>>((const float4*)x,
                                             (uint2*)p_xh, (uint2*)p_xl,
                                             T_ * DIM_ / 4);
    convert_split<<<4 * DIM_ * DIM_ / 1024, 256>>>((const float4*)qkvo,
                                                   (uint2*)p_wh, (uint2*)p_wl,
                                                   4 * DIM_ * DIM_ / 4);

    // 1. qkv = lam0 * x @ Wqkv^T   [3072 x 3072]
    gemm_bf16s<<<dim3(24, 24), 256, GEMM_SMEM>>>(p_xh, p_xl, p_wh, p_wl,
                                                 p_qkv, 3072, lam, 0);

    // 2. rmsnorm + rotary + gates + ve add -> split planes
    postproc_kernel<<<T_, 256>>>(x, ve, vgw, agw, cosb, sinb);

    // 3. attention (tensor cores; k-shift fused; heavy-first)
    attn_mma<<<dim3(T_ / 64, H_), 128, ATTN2_SMEM>>>(seg, bmp);

    // 4. out = lam1 * y @ Wo^T   [3072 x 1024]
    gemm_bf16s<<<dim3(8, 24), 256, GEMM_SMEM>>>(
        p_yh, p_yl, p_wh + (size_t)3 * DIM_ * DIM_, p_wl + (size_t)3 * DIM_ * DIM_,
        out, 1024, lam, 1);
}